// round 1
// baseline (speedup 1.0000x reference)
#include <cuda_runtime.h>
#include <math.h>

// ---------------- problem constants ----------------
#define Bz   8
#define Nn   256
#define Dd   384
#define Ll   6
#define Hh   8
#define FFd  1536
#define Tt   4
#define DhD  48
#define NM1  517            // T + 1 + 2N
#define Sq   1034           // 2*NM1
#define Mrows (Bz*Sq)       // 8272

// ---------------- device scratch ----------------
__device__ float g_src   [Mrows*Dd];
__device__ float g_coords[Mrows*3];
__device__ float g_q     [Mrows*Dd];
__device__ float g_k     [Mrows*Dd];
__device__ float g_v     [Mrows*Dd];
__device__ float g_attn  [Mrows*Dd];
__device__ float g_tmp   [Mrows*Dd];
__device__ float g_ff    [Mrows*FFd];

// ---------------- build src / coords ----------------
__global__ void build_src_kernel(const float* __restrict__ hand_t, const float* __restrict__ head_t,
                                 const float* __restrict__ hand_m1, const float* __restrict__ head_m1,
                                 const float* __restrict__ state_t, const float* __restrict__ state_m1,
                                 const float* __restrict__ tok_m1, const float* __restrict__ tok_t) {
    int idx = blockIdx.x * blockDim.x + threadIdx.x;
    if (idx >= Mrows * Dd) return;
    int d  = idx % Dd;
    int bs = idx / Dd;
    int s  = bs % Sq;
    int b  = bs / Sq;
    int half = (s >= NM1) ? 1 : 0;
    int sl = s - half * NM1;
    float v;
    if (sl == 0)            v = (half ? state_t : state_m1)[b*Dd + d];
    else if (sl <= Nn)      v = (half ? hand_t : hand_m1)[(b*Nn + sl-1)*Dd + d];
    else if (sl <= 2*Nn)    v = (half ? head_t : head_m1)[(b*Nn + sl-1-Nn)*Dd + d];
    else                    v = (half ? tok_t : tok_m1)[(sl-1-2*Nn)*Dd + d];
    g_src[idx] = v;
}

__global__ void build_coords_kernel(const float* __restrict__ ch_t, const float* __restrict__ chd_t,
                                    const float* __restrict__ ch_m1, const float* __restrict__ chd_m1,
                                    const float* __restrict__ tr_t, const float* __restrict__ tr_m1) {
    int idx = blockIdx.x * blockDim.x + threadIdx.x;
    if (idx >= Mrows * 3) return;
    int c  = idx % 3;
    int bs = idx / 3;
    int s  = bs % Sq;
    int b  = bs / Sq;
    int half = (s >= NM1) ? 1 : 0;
    int sl = s - half * NM1;
    float v;
    if (sl == 0 || sl > 2*Nn) v = (half ? tr_t : tr_m1)[b*3 + c];
    else if (sl <= Nn)        v = (half ? ch_t : ch_m1)[(b*Nn + sl-1)*3 + c];
    else                      v = (half ? chd_t : chd_m1)[(b*Nn + sl-1-Nn)*3 + c];
    g_coords[idx] = v;
}

// ---------------- SGEMM: C = A(M,K) * W(N,K)^T + bias ----------------
// mode 0: plain row-major out. mode 1: head layout [B,H,S,Dh]. mode 2: GELU(exact).
#define BM 128
#define BN 64
#define BK 16

__global__ void __launch_bounds__(256)
gemm_kernel(const float* __restrict__ A, const float* __restrict__ W,
            const float* __restrict__ bias, float* __restrict__ C,
            int M, int N, int K, int mode) {
    __shared__ float As[BK][BM + 4];
    __shared__ float Ws[BK][BN + 4];
    int tid = threadIdx.x;
    int tx = tid % 16, ty = tid / 16;
    int m0 = blockIdx.y * BM, n0 = blockIdx.x * BN;

    float acc[8][4] = {};

    for (int k0 = 0; k0 < K; k0 += BK) {
        #pragma unroll
        for (int i = 0; i < 8; i++) {
            int e = tid + i * 256;           // 0..2047
            int r = e / BK, c = e % BK;
            int gm = m0 + r;
            As[c][r] = (gm < M) ? A[(size_t)gm * K + k0 + c] : 0.f;
        }
        #pragma unroll
        for (int i = 0; i < 4; i++) {
            int e = tid + i * 256;           // 0..1023
            int r = e / BK, c = e % BK;
            Ws[c][r] = W[(size_t)(n0 + r) * K + k0 + c];
        }
        __syncthreads();
        #pragma unroll
        for (int kk = 0; kk < BK; kk++) {
            float a[8], w[4];
            #pragma unroll
            for (int i = 0; i < 8; i++) a[i] = As[kk][ty*8 + i];
            #pragma unroll
            for (int j = 0; j < 4; j++) w[j] = Ws[kk][tx*4 + j];
            #pragma unroll
            for (int i = 0; i < 8; i++)
                #pragma unroll
                for (int j = 0; j < 4; j++)
                    acc[i][j] += a[i] * w[j];
        }
        __syncthreads();
    }

    #pragma unroll
    for (int i = 0; i < 8; i++) {
        int m = m0 + ty*8 + i;
        if (m >= M) continue;
        #pragma unroll
        for (int j = 0; j < 4; j++) {
            int n = n0 + tx*4 + j;
            float v = acc[i][j] + bias[n];
            if (mode == 0) {
                C[(size_t)m * N + n] = v;
            } else if (mode == 1) {
                int b = m / Sq, s = m % Sq;
                int h = n / DhD, dd = n % DhD;
                C[(((size_t)b*Hh + h)*Sq + s)*DhD + dd] = v;
            } else {
                v = 0.5f * v * (1.f + erff(v * 0.70710678118654752f));
                C[(size_t)m * N + n] = v;
            }
        }
    }
}

// ---------------- rotary (3-axis) on [B,H,S,Dh] tensor, in place ----------------
__constant__ float c_invfreq[8] = {
    1.0f, 0.31622776601683794f, 0.1f, 0.031622776601683794f,
    0.01f, 0.0031622776601683794f, 0.001f, 0.00031622776601683794f
};

__global__ void rotary_kernel(float* __restrict__ X) {
    int idx = blockIdx.x * blockDim.x + threadIdx.x;   // over B*H*S
    if (idx >= Bz*Hh*Sq) return;
    int s  = idx % Sq;
    int bh = idx / Sq;
    int b  = bh / Hh;
    const float* co = &g_coords[((size_t)b*Sq + s)*3];
    float* x = &X[(size_t)idx * DhD];
    #pragma unroll
    for (int a = 0; a < 3; a++) {
        float coord = co[a];
        #pragma unroll
        for (int j = 0; j < 8; j++) {
            float ang = coord * c_invfreq[j];
            float c, sn;
            __sincosf(ang, &sn, &c);
            float x1 = x[a*16 + j];
            float x2 = x[a*16 + 8 + j];
            x[a*16 + j]     = x1*c - x2*sn;
            x[a*16 + 8 + j] = x1*sn + x2*c;
        }
    }
}

// ---------------- fused attention (flash-style, 1 thread per query) ----------------
#define QPB 128
#define TK  32

__global__ void __launch_bounds__(QPB)
attn_kernel() {
    int bh = blockIdx.y;                 // b*H + h
    int b  = bh / Hh, h = bh % Hh;
    int q0 = blockIdx.x * QPB;
    int qi = q0 + threadIdx.x;
    bool qv = qi < Sq;
    int qq = qv ? qi : (Sq - 1);

    const float scale = 0.14433756729740645f;  // 1/sqrt(48)
    float qreg[DhD];
    {
        const float* qptr = &g_q[((size_t)bh*Sq + qq)*DhD];
        #pragma unroll
        for (int d = 0; d < DhD; d++) qreg[d] = qptr[d] * scale;
    }
    int kl = (qi < NM1) ? NM1 : Sq;
    int last_q = min(q0 + QPB, Sq) - 1;
    int klmax = (last_q >= NM1) ? Sq : NM1;

    __shared__ float Ks[TK][DhD];
    __shared__ float Vs[TK][DhD];
    __shared__ float Sc[QPB][TK + 1];

    float m = -1e30f, l = 0.f;
    float acc[DhD] = {};
    const float* Kbase = &g_k[(size_t)bh*Sq*DhD];
    const float* Vbase = &g_v[(size_t)bh*Sq*DhD];

    for (int k0 = 0; k0 < klmax; k0 += TK) {
        for (int e = threadIdx.x; e < TK*DhD; e += QPB) {
            int kk = e / DhD, d = e % DhD;
            int key = k0 + kk;
            bool ok = key < Sq;
            Ks[kk][d] = ok ? Kbase[(size_t)key*DhD + d] : 0.f;
            Vs[kk][d] = ok ? Vbase[(size_t)key*DhD + d] : 0.f;
        }
        __syncthreads();

        float tmax = -1e30f;
        #pragma unroll 4
        for (int kk = 0; kk < TK; kk++) {
            float s = 0.f;
            #pragma unroll
            for (int d = 0; d < DhD; d++) s += qreg[d] * Ks[kk][d];
            s = (k0 + kk < kl) ? s : -1e30f;
            Sc[threadIdx.x][kk] = s;
            tmax = fmaxf(tmax, s);
        }
        if (tmax > m) {
            float r = __expf(m - tmax);
            l *= r;
            #pragma unroll
            for (int d = 0; d < DhD; d++) acc[d] *= r;
            m = tmax;
        }
        #pragma unroll 2
        for (int kk = 0; kk < TK; kk++) {
            float p = __expf(Sc[threadIdx.x][kk] - m);
            l += p;
            #pragma unroll
            for (int d = 0; d < DhD; d++) acc[d] += p * Vs[kk][d];
        }
        __syncthreads();
    }

    if (qv) {
        float inv = 1.f / l;
        float* o = &g_attn[((size_t)b*Sq + qq)*Dd + h*DhD];
        #pragma unroll
        for (int d = 0; d < DhD; d++) o[d] = acc[d] * inv;
    }
}

// ---------------- residual + LayerNorm (block per row) ----------------
__global__ void __launch_bounds__(128)
add_ln_kernel(const float* X, const float* Yres, float* Out,
              const float* __restrict__ g, const float* __restrict__ be) {
    int row = blockIdx.x;
    __shared__ float red[128];
    const float* x = X + (size_t)row * Dd;
    const float* y = Yres + (size_t)row * Dd;
    float lx[3];
    float sum = 0.f;
    #pragma unroll
    for (int i = 0; i < 3; i++) {
        int d = threadIdx.x + i*128;
        lx[i] = x[d] + y[d];
        sum += lx[i];
    }
    red[threadIdx.x] = sum; __syncthreads();
    for (int st = 64; st > 0; st >>= 1) {
        if (threadIdx.x < st) red[threadIdx.x] += red[threadIdx.x + st];
        __syncthreads();
    }
    float mean = red[0] * (1.f / Dd);
    __syncthreads();
    float vs = 0.f;
    #pragma unroll
    for (int i = 0; i < 3; i++) { float dd = lx[i] - mean; vs += dd*dd; }
    red[threadIdx.x] = vs; __syncthreads();
    for (int st = 64; st > 0; st >>= 1) {
        if (threadIdx.x < st) red[threadIdx.x] += red[threadIdx.x + st];
        __syncthreads();
    }
    float rstd = rsqrtf(red[0] * (1.f / Dd) + 1e-5f);
    #pragma unroll
    for (int i = 0; i < 3; i++) {
        int d = threadIdx.x + i*128;
        Out[(size_t)row*Dd + d] = (lx[i] - mean) * rstd * g[d] + be[d];
    }
}

// ---------------- final extraction ----------------
__global__ void extract_kernel(float* __restrict__ out) {
    int idx = blockIdx.x * blockDim.x + threadIdx.x;
    if (idx >= Bz*Tt*Dd) return;
    int d  = idx % Dd;
    int bt = idx / Dd;
    int t  = bt % Tt;
    int b  = bt / Tt;
    out[idx] = g_src[((size_t)b*Sq + (Sq - Tt + t))*Dd + d];
}

// ---------------- host launcher ----------------
extern "C" void kernel_launch(void* const* d_in, const int* in_sizes, int n_in,
                              void* d_out, int out_size) {
    const float* hand_t   = (const float*)d_in[0];
    const float* head_t   = (const float*)d_in[1];
    const float* hand_m1  = (const float*)d_in[2];
    const float* head_m1  = (const float*)d_in[3];
    const float* c_hand_t = (const float*)d_in[4];
    const float* c_head_t = (const float*)d_in[5];
    const float* c_hand_m1= (const float*)d_in[6];
    const float* c_head_m1= (const float*)d_in[7];
    const float* state_t  = (const float*)d_in[8];
    const float* state_m1 = (const float*)d_in[9];
    const float* tr_t     = (const float*)d_in[10];
    const float* tr_m1    = (const float*)d_in[11];
    const float* tokens_m1= (const float*)d_in[12];
    const float* tokens_t = (const float*)d_in[13];
    const float* Wq = (const float*)d_in[14];
    const float* bq = (const float*)d_in[15];
    const float* Wk = (const float*)d_in[16];
    const float* bk = (const float*)d_in[17];
    const float* Wv = (const float*)d_in[18];
    const float* bv = (const float*)d_in[19];
    const float* Wo = (const float*)d_in[20];
    const float* bo = (const float*)d_in[21];
    const float* W1 = (const float*)d_in[22];
    const float* b1 = (const float*)d_in[23];
    const float* W2 = (const float*)d_in[24];
    const float* b2 = (const float*)d_in[25];
    const float* g1 = (const float*)d_in[26];
    const float* be1= (const float*)d_in[27];
    const float* g2 = (const float*)d_in[28];
    const float* be2= (const float*)d_in[29];

    float *src, *q, *k, *v, *attn, *tmp, *ff;
    cudaGetSymbolAddress((void**)&src,  g_src);
    cudaGetSymbolAddress((void**)&q,    g_q);
    cudaGetSymbolAddress((void**)&k,    g_k);
    cudaGetSymbolAddress((void**)&v,    g_v);
    cudaGetSymbolAddress((void**)&attn, g_attn);
    cudaGetSymbolAddress((void**)&tmp,  g_tmp);
    cudaGetSymbolAddress((void**)&ff,   g_ff);

    build_src_kernel<<<(Mrows*Dd + 255)/256, 256>>>(hand_t, head_t, hand_m1, head_m1,
                                                    state_t, state_m1, tokens_m1, tokens_t);
    build_coords_kernel<<<(Mrows*3 + 255)/256, 256>>>(c_hand_t, c_head_t, c_hand_m1, c_head_m1,
                                                      tr_t, tr_m1);

    dim3 gD(Dd/BN,  (Mrows + BM - 1)/BM);
    dim3 gF(FFd/BN, (Mrows + BM - 1)/BM);
    dim3 gAttn((Sq + QPB - 1)/QPB, Bz*Hh);

    for (int l = 0; l < Ll; l++) {
        const float* wq = Wq + (size_t)l*Dd*Dd;  const float* bql = bq + (size_t)l*Dd;
        const float* wk = Wk + (size_t)l*Dd*Dd;  const float* bkl = bk + (size_t)l*Dd;
        const float* wv = Wv + (size_t)l*Dd*Dd;  const float* bvl = bv + (size_t)l*Dd;
        const float* wo = Wo + (size_t)l*Dd*Dd;  const float* bol = bo + (size_t)l*Dd;
        const float* w1 = W1 + (size_t)l*FFd*Dd; const float* b1l = b1 + (size_t)l*FFd;
        const float* w2 = W2 + (size_t)l*Dd*FFd; const float* b2l = b2 + (size_t)l*Dd;
        const float* g1l = g1 + (size_t)l*Dd;    const float* be1l = be1 + (size_t)l*Dd;
        const float* g2l = g2 + (size_t)l*Dd;    const float* be2l = be2 + (size_t)l*Dd;

        gemm_kernel<<<gD, 256>>>(src, wq, bql, q, Mrows, Dd, Dd, 1);
        gemm_kernel<<<gD, 256>>>(src, wk, bkl, k, Mrows, Dd, Dd, 1);
        gemm_kernel<<<gD, 256>>>(src, wv, bvl, v, Mrows, Dd, Dd, 1);

        rotary_kernel<<<(Bz*Hh*Sq + 127)/128, 128>>>(q);
        rotary_kernel<<<(Bz*Hh*Sq + 127)/128, 128>>>(k);

        attn_kernel<<<gAttn, QPB>>>();

        gemm_kernel<<<gD, 256>>>(attn, wo, bol, tmp, Mrows, Dd, Dd, 0);
        add_ln_kernel<<<Mrows, 128>>>(src, tmp, src, g1l, be1l);

        gemm_kernel<<<gF, 256>>>(src, w1, b1l, ff, Mrows, FFd, Dd, 2);
        gemm_kernel<<<gD, 256>>>(ff, w2, b2l, tmp, Mrows, Dd, FFd, 0);
        add_ln_kernel<<<Mrows, 128>>>(src, tmp, src, g2l, be2l);
    }

    extract_kernel<<<(Bz*Tt*Dd + 255)/256, 256>>>((float*)d_out);
}

// round 3
// speedup vs baseline: 1.4390x; 1.4390x over previous
#include <cuda_runtime.h>
#include <cstdint>
#include <math.h>

// ---------------- problem constants ----------------
#define Bz   8
#define Nn   256
#define Dd   384
#define Ll   6
#define Hh   8
#define FFd  1536
#define Tt   4
#define DhD  48
#define NM1  517            // T + 1 + 2N
#define Sq   1034           // 2*NM1
#define Mrows (Bz*Sq)       // 8272

// ---------------- device scratch ----------------
__device__ float g_src   [Mrows*Dd];
__device__ float g_coords[Mrows*3];
__device__ float g_q     [Mrows*Dd];
__device__ float g_k     [Mrows*Dd];
__device__ float g_v     [Mrows*Dd];
__device__ float g_attn  [Mrows*Dd];
__device__ float g_tmp   [Mrows*Dd];
__device__ float g_ff    [Mrows*FFd];

// ---------------- build src / coords ----------------
__global__ void build_src_kernel(const float* __restrict__ hand_t, const float* __restrict__ head_t,
                                 const float* __restrict__ hand_m1, const float* __restrict__ head_m1,
                                 const float* __restrict__ state_t, const float* __restrict__ state_m1,
                                 const float* __restrict__ tok_m1, const float* __restrict__ tok_t) {
    int idx = blockIdx.x * blockDim.x + threadIdx.x;
    if (idx >= Mrows * Dd) return;
    int d  = idx % Dd;
    int bs = idx / Dd;
    int s  = bs % Sq;
    int b  = bs / Sq;
    int half = (s >= NM1) ? 1 : 0;
    int sl = s - half * NM1;
    float v;
    if (sl == 0)            v = (half ? state_t : state_m1)[b*Dd + d];
    else if (sl <= Nn)      v = (half ? hand_t : hand_m1)[(b*Nn + sl-1)*Dd + d];
    else if (sl <= 2*Nn)    v = (half ? head_t : head_m1)[(b*Nn + sl-1-Nn)*Dd + d];
    else                    v = (half ? tok_t : tok_m1)[(sl-1-2*Nn)*Dd + d];
    g_src[idx] = v;
}

__global__ void build_coords_kernel(const float* __restrict__ ch_t, const float* __restrict__ chd_t,
                                    const float* __restrict__ ch_m1, const float* __restrict__ chd_m1,
                                    const float* __restrict__ tr_t, const float* __restrict__ tr_m1) {
    int idx = blockIdx.x * blockDim.x + threadIdx.x;
    if (idx >= Mrows * 3) return;
    int c  = idx % 3;
    int bs = idx / 3;
    int s  = bs % Sq;
    int b  = bs / Sq;
    int half = (s >= NM1) ? 1 : 0;
    int sl = s - half * NM1;
    float v;
    if (sl == 0 || sl > 2*Nn) v = (half ? tr_t : tr_m1)[b*3 + c];
    else if (sl <= Nn)        v = (half ? ch_t : ch_m1)[(b*Nn + sl-1)*3 + c];
    else                      v = (half ? chd_t : chd_m1)[(b*Nn + sl-1-Nn)*3 + c];
    g_coords[idx] = v;
}

// ---------------- tf32 mma.sync GEMM: C = A(M,K) * W(N,K)^T + bias ----------------
// tile 128x64x32, 256 threads (8 warps, 4x2), warp tile 32x32 (2x4 m16n8k8 frags).
// mode 0: plain row-major. mode 1: head layout [B,H,S,Dh]. mode 2: exact GELU.

#define PAD_STR 36                       // floats per smem row (32 + 4 pad)
#define SA_FLOATS (128 * PAD_STR)        // 4608
#define SB_FLOATS (64 * PAD_STR)         // 2304
#define GSM_TOTAL ((2 * SA_FLOATS + 2 * SB_FLOATS) * 4)   // 55296 bytes

__device__ __forceinline__ uint32_t f2tf32(float f) {
    uint32_t u;
    asm("cvt.rna.tf32.f32 %0, %1;" : "=r"(u) : "f"(f));
    return u;
}

#define MMA_TF32(d, a, b) \
    asm("mma.sync.aligned.m16n8k8.row.col.f32.tf32.tf32.f32 " \
        "{%0,%1,%2,%3}, {%4,%5,%6,%7}, {%8,%9}, {%0,%1,%2,%3};" \
        : "+f"((d)[0]), "+f"((d)[1]), "+f"((d)[2]), "+f"((d)[3]) \
        : "r"((a)[0]), "r"((a)[1]), "r"((a)[2]), "r"((a)[3]), \
          "r"((b)[0]), "r"((b)[1]))

__device__ __forceinline__ void gload_chunk(const float* __restrict__ A, const float* __restrict__ W,
                                            int M, int K, int m0, int n0, int k0,
                                            float4* pa, float4* pb) {
    int tid = threadIdx.x;
    #pragma unroll
    for (int i = 0; i < 4; i++) {                 // A: 128x32 -> 1024 float4
        int e = tid + i * 256;
        int r = e >> 3, c4 = e & 7;
        int gm = m0 + r;
        pa[i] = (gm < M) ? *(const float4*)&A[(size_t)gm * K + k0 + c4 * 4]
                         : make_float4(0.f, 0.f, 0.f, 0.f);
    }
    #pragma unroll
    for (int i = 0; i < 2; i++) {                 // B: 64x32 -> 512 float4
        int e = tid + i * 256;
        int r = e >> 3, c4 = e & 7;
        pb[i] = *(const float4*)&W[(size_t)(n0 + r) * K + k0 + c4 * 4];
    }
}

__device__ __forceinline__ void sstore_chunk(uint32_t* sA, uint32_t* sB,
                                             const float4* pa, const float4* pb) {
    int tid = threadIdx.x;
    #pragma unroll
    for (int i = 0; i < 4; i++) {
        int e = tid + i * 256;
        int r = e >> 3, c4 = e & 7;
        uint4 u;
        u.x = f2tf32(pa[i].x); u.y = f2tf32(pa[i].y);
        u.z = f2tf32(pa[i].z); u.w = f2tf32(pa[i].w);
        *(uint4*)&sA[r * PAD_STR + c4 * 4] = u;   // 144B row stride, 16B aligned
    }
    #pragma unroll
    for (int i = 0; i < 2; i++) {
        int e = tid + i * 256;
        int r = e >> 3, c4 = e & 7;
        uint4 u;
        u.x = f2tf32(pb[i].x); u.y = f2tf32(pb[i].y);
        u.z = f2tf32(pb[i].z); u.w = f2tf32(pb[i].w);
        *(uint4*)&sB[r * PAD_STR + c4 * 4] = u;
    }
}

__global__ void __launch_bounds__(256, 2)
tf32_mma_gemm(const float* __restrict__ A, const float* __restrict__ W,
              const float* __restrict__ bias, float* __restrict__ C,
              int M, int N, int K, int mode) {
    extern __shared__ uint32_t smu[];
    uint32_t* sAb[2] = { smu, smu + SA_FLOATS };
    uint32_t* sBb[2] = { smu + 2 * SA_FLOATS, smu + 2 * SA_FLOATS + SB_FLOATS };

    int tid = threadIdx.x;
    int lane = tid & 31, wid = tid >> 5;
    int wm = wid & 3, wn = wid >> 2;              // warp grid 4 (M) x 2 (N)
    int g = lane >> 2, t = lane & 3;
    int m0 = blockIdx.y * 128, n0 = blockIdx.x * 64;
    int NC = K / 32;

    float4 pa[4]; float4 pb[2];
    gload_chunk(A, W, M, K, m0, n0, 0, pa, pb);
    sstore_chunk(sAb[0], sBb[0], pa, pb);
    __syncthreads();

    float acc[2][4][4] = {};

    for (int c = 0; c < NC; c++) {
        const uint32_t* cA = sAb[c & 1];
        const uint32_t* cB = sBb[c & 1];
        if (c + 1 < NC) gload_chunk(A, W, M, K, m0, n0, (c + 1) * 32, pa, pb);

        #pragma unroll
        for (int kk = 0; kk < 4; kk++) {
            uint32_t af[2][4], bf[4][2];
            #pragma unroll
            for (int mi = 0; mi < 2; mi++) {
                int base = (wm * 32 + mi * 16 + g) * PAD_STR + kk * 8 + t;
                af[mi][0] = cA[base];
                af[mi][1] = cA[base + 8 * PAD_STR];
                af[mi][2] = cA[base + 4];
                af[mi][3] = cA[base + 8 * PAD_STR + 4];
            }
            #pragma unroll
            for (int ni = 0; ni < 4; ni++) {
                int bb = (wn * 32 + ni * 8 + g) * PAD_STR + kk * 8 + t;
                bf[ni][0] = cB[bb];
                bf[ni][1] = cB[bb + 4];
            }
            #pragma unroll
            for (int mi = 0; mi < 2; mi++)
                #pragma unroll
                for (int ni = 0; ni < 4; ni++)
                    MMA_TF32(acc[mi][ni], af[mi], bf[ni]);
        }
        __syncthreads();
        if (c + 1 < NC) {
            sstore_chunk(sAb[(c + 1) & 1], sBb[(c + 1) & 1], pa, pb);
            __syncthreads();
        }
    }

    // epilogue: c0 (row g, col 2t), c1 (row g, col 2t+1), c2/c3 at row g+8
    #pragma unroll
    for (int mi = 0; mi < 2; mi++) {
        #pragma unroll
        for (int half = 0; half < 2; half++) {
            int row = m0 + wm * 32 + mi * 16 + g + half * 8;
            if (row >= M) continue;
            #pragma unroll
            for (int ni = 0; ni < 4; ni++) {
                int col = n0 + wn * 32 + ni * 8 + 2 * t;
                float v0 = acc[mi][ni][half * 2 + 0] + bias[col];
                float v1 = acc[mi][ni][half * 2 + 1] + bias[col + 1];
                if (mode == 0) {
                    *(float2*)&C[(size_t)row * N + col] = make_float2(v0, v1);
                } else if (mode == 1) {
                    int b = row / Sq, s = row % Sq;
                    int h0 = col / DhD, d0 = col % DhD;
                    int h1 = (col + 1) / DhD, d1 = (col + 1) % DhD;
                    C[(((size_t)b * Hh + h0) * Sq + s) * DhD + d0] = v0;
                    C[(((size_t)b * Hh + h1) * Sq + s) * DhD + d1] = v1;
                } else {
                    v0 = 0.5f * v0 * (1.f + erff(v0 * 0.70710678118654752f));
                    v1 = 0.5f * v1 * (1.f + erff(v1 * 0.70710678118654752f));
                    *(float2*)&C[(size_t)row * N + col] = make_float2(v0, v1);
                }
            }
        }
    }
}

// ---------------- rotary (3-axis) on [B,H,S,Dh] tensor, in place ----------------
__constant__ float c_invfreq[8] = {
    1.0f, 0.31622776601683794f, 0.1f, 0.031622776601683794f,
    0.01f, 0.0031622776601683794f, 0.001f, 0.00031622776601683794f
};

__global__ void rotary_kernel(float* __restrict__ X) {
    int idx = blockIdx.x * blockDim.x + threadIdx.x;   // over B*H*S
    if (idx >= Bz*Hh*Sq) return;
    int s  = idx % Sq;
    int bh = idx / Sq;
    int b  = bh / Hh;
    const float* co = &g_coords[((size_t)b*Sq + s)*3];
    float* x = &X[(size_t)idx * DhD];
    #pragma unroll
    for (int a = 0; a < 3; a++) {
        float coord = co[a];
        #pragma unroll
        for (int j = 0; j < 8; j++) {
            float ang = coord * c_invfreq[j];
            float c, sn;
            __sincosf(ang, &sn, &c);
            float x1 = x[a*16 + j];
            float x2 = x[a*16 + 8 + j];
            x[a*16 + j]     = x1*c - x2*sn;
            x[a*16 + 8 + j] = x1*sn + x2*c;
        }
    }
}

// ---------------- fused attention (flash-style, 1 thread per query) ----------------
#define QPB 128
#define TK  32

__global__ void __launch_bounds__(QPB)
attn_kernel() {
    int bh = blockIdx.y;                 // b*H + h
    int b  = bh / Hh, h = bh % Hh;
    int q0 = blockIdx.x * QPB;
    int qi = q0 + threadIdx.x;
    bool qv = qi < Sq;
    int qq = qv ? qi : (Sq - 1);

    const float scale = 0.14433756729740645f;  // 1/sqrt(48)
    float qreg[DhD];
    {
        const float* qptr = &g_q[((size_t)bh*Sq + qq)*DhD];
        #pragma unroll
        for (int d = 0; d < DhD; d++) qreg[d] = qptr[d] * scale;
    }
    int kl = (qi < NM1) ? NM1 : Sq;
    int last_q = min(q0 + QPB, Sq) - 1;
    int klmax = (last_q >= NM1) ? Sq : NM1;

    __shared__ float Ks[TK][DhD];
    __shared__ float Vs[TK][DhD];
    __shared__ float Sc[QPB][TK + 1];

    float m = -1e30f, l = 0.f;
    float acc[DhD] = {};
    const float* Kbase = &g_k[(size_t)bh*Sq*DhD];
    const float* Vbase = &g_v[(size_t)bh*Sq*DhD];

    for (int k0 = 0; k0 < klmax; k0 += TK) {
        for (int e = threadIdx.x; e < TK*DhD; e += QPB) {
            int kk = e / DhD, d = e % DhD;
            int key = k0 + kk;
            bool ok = key < Sq;
            Ks[kk][d] = ok ? Kbase[(size_t)key*DhD + d] : 0.f;
            Vs[kk][d] = ok ? Vbase[(size_t)key*DhD + d] : 0.f;
        }
        __syncthreads();

        float tmax = -1e30f;
        #pragma unroll 4
        for (int kk = 0; kk < TK; kk++) {
            float s = 0.f;
            #pragma unroll
            for (int d = 0; d < DhD; d++) s += qreg[d] * Ks[kk][d];
            s = (k0 + kk < kl) ? s : -1e30f;
            Sc[threadIdx.x][kk] = s;
            tmax = fmaxf(tmax, s);
        }
        if (tmax > m) {
            float r = __expf(m - tmax);
            l *= r;
            #pragma unroll
            for (int d = 0; d < DhD; d++) acc[d] *= r;
            m = tmax;
        }
        #pragma unroll 2
        for (int kk = 0; kk < TK; kk++) {
            float p = __expf(Sc[threadIdx.x][kk] - m);
            l += p;
            #pragma unroll
            for (int d = 0; d < DhD; d++) acc[d] += p * Vs[kk][d];
        }
        __syncthreads();
    }

    if (qv) {
        float inv = 1.f / l;
        float* o = &g_attn[((size_t)b*Sq + qq)*Dd + h*DhD];
        #pragma unroll
        for (int d = 0; d < DhD; d++) o[d] = acc[d] * inv;
    }
}

// ---------------- residual + LayerNorm (block per row) ----------------
__global__ void __launch_bounds__(128)
add_ln_kernel(const float* X, const float* Yres, float* Out,
              const float* __restrict__ g, const float* __restrict__ be) {
    int row = blockIdx.x;
    __shared__ float red[128];
    const float* x = X + (size_t)row * Dd;
    const float* y = Yres + (size_t)row * Dd;
    float lx[3];
    float sum = 0.f;
    #pragma unroll
    for (int i = 0; i < 3; i++) {
        int d = threadIdx.x + i*128;
        lx[i] = x[d] + y[d];
        sum += lx[i];
    }
    red[threadIdx.x] = sum; __syncthreads();
    for (int st = 64; st > 0; st >>= 1) {
        if (threadIdx.x < st) red[threadIdx.x] += red[threadIdx.x + st];
        __syncthreads();
    }
    float mean = red[0] * (1.f / Dd);
    __syncthreads();
    float vs = 0.f;
    #pragma unroll
    for (int i = 0; i < 3; i++) { float dd = lx[i] - mean; vs += dd*dd; }
    red[threadIdx.x] = vs; __syncthreads();
    for (int st = 64; st > 0; st >>= 1) {
        if (threadIdx.x < st) red[threadIdx.x] += red[threadIdx.x + st];
        __syncthreads();
    }
    float rstd = rsqrtf(red[0] * (1.f / Dd) + 1e-5f);
    #pragma unroll
    for (int i = 0; i < 3; i++) {
        int d = threadIdx.x + i*128;
        Out[(size_t)row*Dd + d] = (lx[i] - mean) * rstd * g[d] + be[d];
    }
}

// ---------------- final extraction ----------------
__global__ void extract_kernel(float* __restrict__ out) {
    int idx = blockIdx.x * blockDim.x + threadIdx.x;
    if (idx >= Bz*Tt*Dd) return;
    int d  = idx % Dd;
    int bt = idx / Dd;
    int t  = bt % Tt;
    int b  = bt / Tt;
    out[idx] = g_src[((size_t)b*Sq + (Sq - Tt + t))*Dd + d];
}

// ---------------- host launcher ----------------
extern "C" void kernel_launch(void* const* d_in, const int* in_sizes, int n_in,
                              void* d_out, int out_size) {
    const float* hand_t   = (const float*)d_in[0];
    const float* head_t   = (const float*)d_in[1];
    const float* hand_m1  = (const float*)d_in[2];
    const float* head_m1  = (const float*)d_in[3];
    const float* c_hand_t = (const float*)d_in[4];
    const float* c_head_t = (const float*)d_in[5];
    const float* c_hand_m1= (const float*)d_in[6];
    const float* c_head_m1= (const float*)d_in[7];
    const float* state_t  = (const float*)d_in[8];
    const float* state_m1 = (const float*)d_in[9];
    const float* tr_t     = (const float*)d_in[10];
    const float* tr_m1    = (const float*)d_in[11];
    const float* tokens_m1= (const float*)d_in[12];
    const float* tokens_t = (const float*)d_in[13];
    const float* Wq = (const float*)d_in[14];
    const float* bq = (const float*)d_in[15];
    const float* Wk = (const float*)d_in[16];
    const float* bk = (const float*)d_in[17];
    const float* Wv = (const float*)d_in[18];
    const float* bv = (const float*)d_in[19];
    const float* Wo = (const float*)d_in[20];
    const float* bo = (const float*)d_in[21];
    const float* W1 = (const float*)d_in[22];
    const float* b1 = (const float*)d_in[23];
    const float* W2 = (const float*)d_in[24];
    const float* b2 = (const float*)d_in[25];
    const float* g1 = (const float*)d_in[26];
    const float* be1= (const float*)d_in[27];
    const float* g2 = (const float*)d_in[28];
    const float* be2= (const float*)d_in[29];

    float *src, *q, *k, *v, *attn, *tmp, *ff;
    cudaGetSymbolAddress((void**)&src,  g_src);
    cudaGetSymbolAddress((void**)&q,    g_q);
    cudaGetSymbolAddress((void**)&k,    g_k);
    cudaGetSymbolAddress((void**)&v,    g_v);
    cudaGetSymbolAddress((void**)&attn, g_attn);
    cudaGetSymbolAddress((void**)&tmp,  g_tmp);
    cudaGetSymbolAddress((void**)&ff,   g_ff);

    cudaFuncSetAttribute(tf32_mma_gemm, cudaFuncAttributeMaxDynamicSharedMemorySize, GSM_TOTAL);

    build_src_kernel<<<(Mrows*Dd + 255)/256, 256>>>(hand_t, head_t, hand_m1, head_m1,
                                                    state_t, state_m1, tokens_m1, tokens_t);
    build_coords_kernel<<<(Mrows*3 + 255)/256, 256>>>(c_hand_t, c_head_t, c_hand_m1, c_head_m1,
                                                      tr_t, tr_m1);

    dim3 gD(Dd/64,  (Mrows + 127)/128);   // (6, 65)
    dim3 gF(FFd/64, (Mrows + 127)/128);   // (24, 65)
    dim3 gAttn((Sq + QPB - 1)/QPB, Bz*Hh);

    for (int l = 0; l < Ll; l++) {
        const float* wq = Wq + (size_t)l*Dd*Dd;  const float* bql = bq + (size_t)l*Dd;
        const float* wk = Wk + (size_t)l*Dd*Dd;  const float* bkl = bk + (size_t)l*Dd;
        const float* wv = Wv + (size_t)l*Dd*Dd;  const float* bvl = bv + (size_t)l*Dd;
        const float* wo = Wo + (size_t)l*Dd*Dd;  const float* bol = bo + (size_t)l*Dd;
        const float* w1 = W1 + (size_t)l*FFd*Dd; const float* b1l = b1 + (size_t)l*FFd;
        const float* w2 = W2 + (size_t)l*Dd*FFd; const float* b2l = b2 + (size_t)l*Dd;
        const float* g1l = g1 + (size_t)l*Dd;    const float* be1l = be1 + (size_t)l*Dd;
        const float* g2l = g2 + (size_t)l*Dd;    const float* be2l = be2 + (size_t)l*Dd;

        tf32_mma_gemm<<<gD, 256, GSM_TOTAL>>>(src, wq, bql, q, Mrows, Dd, Dd, 1);
        tf32_mma_gemm<<<gD, 256, GSM_TOTAL>>>(src, wk, bkl, k, Mrows, Dd, Dd, 1);
        tf32_mma_gemm<<<gD, 256, GSM_TOTAL>>>(src, wv, bvl, v, Mrows, Dd, Dd, 1);

        rotary_kernel<<<(Bz*Hh*Sq + 127)/128, 128>>>(q);
        rotary_kernel<<<(Bz*Hh*Sq + 127)/128, 128>>>(k);

        attn_kernel<<<gAttn, QPB>>>();

        tf32_mma_gemm<<<gD, 256, GSM_TOTAL>>>(attn, wo, bol, tmp, Mrows, Dd, Dd, 0);
        add_ln_kernel<<<Mrows, 128>>>(src, tmp, src, g1l, be1l);

        tf32_mma_gemm<<<gF, 256, GSM_TOTAL>>>(src, w1, b1l, ff, Mrows, FFd, Dd, 2);
        tf32_mma_gemm<<<gD, 256, GSM_TOTAL>>>(ff, w2, b2l, tmp, Mrows, Dd, FFd, 0);
        add_ln_kernel<<<Mrows, 128>>>(src, tmp, src, g2l, be2l);
    }

    extract_kernel<<<(Bz*Tt*Dd + 255)/256, 256>>>((float*)d_out);
}

// round 4
// speedup vs baseline: 2.1813x; 1.5158x over previous
#include <cuda_runtime.h>
#include <cstdint>
#include <math.h>

// ---------------- problem constants ----------------
#define Bz   8
#define Nn   256
#define Dd   384
#define Ll   6
#define Hh   8
#define FFd  1536
#define Tt   4
#define DhD  48
#define NM1  517            // T + 1 + 2N
#define Sq   1034           // 2*NM1
#define Mrows (Bz*Sq)       // 8272

// ---------------- device scratch ----------------
__device__ float g_src   [Mrows*Dd];
__device__ float g_coords[Mrows*3];
__device__ float g_q     [Mrows*Dd];
__device__ float g_k     [Mrows*Dd];
__device__ float g_v     [Mrows*Dd];
__device__ float g_attn  [Mrows*Dd];
__device__ float g_tmp   [Mrows*Dd];
__device__ float g_ff    [Mrows*FFd];

// ---------------- build src / coords ----------------
__global__ void build_src_kernel(const float* __restrict__ hand_t, const float* __restrict__ head_t,
                                 const float* __restrict__ hand_m1, const float* __restrict__ head_m1,
                                 const float* __restrict__ state_t, const float* __restrict__ state_m1,
                                 const float* __restrict__ tok_m1, const float* __restrict__ tok_t) {
    int idx = blockIdx.x * blockDim.x + threadIdx.x;
    if (idx >= Mrows * Dd) return;
    int d  = idx % Dd;
    int bs = idx / Dd;
    int s  = bs % Sq;
    int b  = bs / Sq;
    int half = (s >= NM1) ? 1 : 0;
    int sl = s - half * NM1;
    float v;
    if (sl == 0)            v = (half ? state_t : state_m1)[b*Dd + d];
    else if (sl <= Nn)      v = (half ? hand_t : hand_m1)[(b*Nn + sl-1)*Dd + d];
    else if (sl <= 2*Nn)    v = (half ? head_t : head_m1)[(b*Nn + sl-1-Nn)*Dd + d];
    else                    v = (half ? tok_t : tok_m1)[(sl-1-2*Nn)*Dd + d];
    g_src[idx] = v;
}

__global__ void build_coords_kernel(const float* __restrict__ ch_t, const float* __restrict__ chd_t,
                                    const float* __restrict__ ch_m1, const float* __restrict__ chd_m1,
                                    const float* __restrict__ tr_t, const float* __restrict__ tr_m1) {
    int idx = blockIdx.x * blockDim.x + threadIdx.x;
    if (idx >= Mrows * 3) return;
    int c  = idx % 3;
    int bs = idx / 3;
    int s  = bs % Sq;
    int b  = bs / Sq;
    int half = (s >= NM1) ? 1 : 0;
    int sl = s - half * NM1;
    float v;
    if (sl == 0 || sl > 2*Nn) v = (half ? tr_t : tr_m1)[b*3 + c];
    else if (sl <= Nn)        v = (half ? ch_t : ch_m1)[(b*Nn + sl-1)*3 + c];
    else                      v = (half ? chd_t : chd_m1)[(b*Nn + sl-1-Nn)*3 + c];
    g_coords[idx] = v;
}

// ---------------- shared mma helpers ----------------
__device__ __forceinline__ uint32_t f2tf32(float f) {
    uint32_t u;
    asm("cvt.rna.tf32.f32 %0, %1;" : "=r"(u) : "f"(f));
    return u;
}

#define MMA_TF32(d, a, b) \
    asm("mma.sync.aligned.m16n8k8.row.col.f32.tf32.tf32.f32 " \
        "{%0,%1,%2,%3}, {%4,%5,%6,%7}, {%8,%9}, {%0,%1,%2,%3};" \
        : "+f"((d)[0]), "+f"((d)[1]), "+f"((d)[2]), "+f"((d)[3]) \
        : "r"((a)[0]), "r"((a)[1]), "r"((a)[2]), "r"((a)[3]), \
          "r"((b)[0]), "r"((b)[1]))

// ---------------- tf32 mma.sync GEMM: C = A(M,K) * W(N,K)^T + bias ----------------
// tile 128x64x32, 256 threads (8 warps, 4x2), warp tile 32x32 (2x4 m16n8k8 frags).
// mode 0: plain row-major. mode 1: head layout [B,H,S,Dh]. mode 2: exact GELU.

#define PAD_STR 36                       // floats per smem row (32 + 4 pad)
#define SA_FLOATS (128 * PAD_STR)        // 4608
#define SB_FLOATS (64 * PAD_STR)         // 2304
#define GSM_TOTAL ((2 * SA_FLOATS + 2 * SB_FLOATS) * 4)   // 55296 bytes

__device__ __forceinline__ void gload_chunk(const float* __restrict__ A, const float* __restrict__ W,
                                            int M, int K, int m0, int n0, int k0,
                                            float4* pa, float4* pb) {
    int tid = threadIdx.x;
    #pragma unroll
    for (int i = 0; i < 4; i++) {                 // A: 128x32 -> 1024 float4
        int e = tid + i * 256;
        int r = e >> 3, c4 = e & 7;
        int gm = m0 + r;
        pa[i] = (gm < M) ? *(const float4*)&A[(size_t)gm * K + k0 + c4 * 4]
                         : make_float4(0.f, 0.f, 0.f, 0.f);
    }
    #pragma unroll
    for (int i = 0; i < 2; i++) {                 // B: 64x32 -> 512 float4
        int e = tid + i * 256;
        int r = e >> 3, c4 = e & 7;
        pb[i] = *(const float4*)&W[(size_t)(n0 + r) * K + k0 + c4 * 4];
    }
}

__device__ __forceinline__ void sstore_chunk(uint32_t* sA, uint32_t* sB,
                                             const float4* pa, const float4* pb) {
    int tid = threadIdx.x;
    #pragma unroll
    for (int i = 0; i < 4; i++) {
        int e = tid + i * 256;
        int r = e >> 3, c4 = e & 7;
        uint4 u;
        u.x = f2tf32(pa[i].x); u.y = f2tf32(pa[i].y);
        u.z = f2tf32(pa[i].z); u.w = f2tf32(pa[i].w);
        *(uint4*)&sA[r * PAD_STR + c4 * 4] = u;   // 144B row stride, 16B aligned
    }
    #pragma unroll
    for (int i = 0; i < 2; i++) {
        int e = tid + i * 256;
        int r = e >> 3, c4 = e & 7;
        uint4 u;
        u.x = f2tf32(pb[i].x); u.y = f2tf32(pb[i].y);
        u.z = f2tf32(pb[i].z); u.w = f2tf32(pb[i].w);
        *(uint4*)&sB[r * PAD_STR + c4 * 4] = u;
    }
}

__global__ void __launch_bounds__(256, 2)
tf32_mma_gemm(const float* __restrict__ A, const float* __restrict__ W,
              const float* __restrict__ bias, float* __restrict__ C,
              int M, int N, int K, int mode) {
    extern __shared__ uint32_t smu[];
    uint32_t* sAb[2] = { smu, smu + SA_FLOATS };
    uint32_t* sBb[2] = { smu + 2 * SA_FLOATS, smu + 2 * SA_FLOATS + SB_FLOATS };

    int tid = threadIdx.x;
    int lane = tid & 31, wid = tid >> 5;
    int wm = wid & 3, wn = wid >> 2;              // warp grid 4 (M) x 2 (N)
    int g = lane >> 2, t = lane & 3;
    int m0 = blockIdx.y * 128, n0 = blockIdx.x * 64;
    int NC = K / 32;

    float4 pa[4]; float4 pb[2];
    gload_chunk(A, W, M, K, m0, n0, 0, pa, pb);
    sstore_chunk(sAb[0], sBb[0], pa, pb);
    __syncthreads();

    float acc[2][4][4] = {};

    for (int c = 0; c < NC; c++) {
        const uint32_t* cA = sAb[c & 1];
        const uint32_t* cB = sBb[c & 1];
        if (c + 1 < NC) gload_chunk(A, W, M, K, m0, n0, (c + 1) * 32, pa, pb);

        #pragma unroll
        for (int kk = 0; kk < 4; kk++) {
            uint32_t af[2][4], bf[4][2];
            #pragma unroll
            for (int mi = 0; mi < 2; mi++) {
                int base = (wm * 32 + mi * 16 + g) * PAD_STR + kk * 8 + t;
                af[mi][0] = cA[base];
                af[mi][1] = cA[base + 8 * PAD_STR];
                af[mi][2] = cA[base + 4];
                af[mi][3] = cA[base + 8 * PAD_STR + 4];
            }
            #pragma unroll
            for (int ni = 0; ni < 4; ni++) {
                int bb = (wn * 32 + ni * 8 + g) * PAD_STR + kk * 8 + t;
                bf[ni][0] = cB[bb];
                bf[ni][1] = cB[bb + 4];
            }
            #pragma unroll
            for (int mi = 0; mi < 2; mi++)
                #pragma unroll
                for (int ni = 0; ni < 4; ni++)
                    MMA_TF32(acc[mi][ni], af[mi], bf[ni]);
        }
        __syncthreads();
        if (c + 1 < NC) {
            sstore_chunk(sAb[(c + 1) & 1], sBb[(c + 1) & 1], pa, pb);
            __syncthreads();
        }
    }

    #pragma unroll
    for (int mi = 0; mi < 2; mi++) {
        #pragma unroll
        for (int half = 0; half < 2; half++) {
            int row = m0 + wm * 32 + mi * 16 + g + half * 8;
            if (row >= M) continue;
            #pragma unroll
            for (int ni = 0; ni < 4; ni++) {
                int col = n0 + wn * 32 + ni * 8 + 2 * t;
                float v0 = acc[mi][ni][half * 2 + 0] + bias[col];
                float v1 = acc[mi][ni][half * 2 + 1] + bias[col + 1];
                if (mode == 0) {
                    *(float2*)&C[(size_t)row * N + col] = make_float2(v0, v1);
                } else if (mode == 1) {
                    int b = row / Sq, s = row % Sq;
                    int h0 = col / DhD, d0 = col % DhD;
                    int h1 = (col + 1) / DhD, d1 = (col + 1) % DhD;
                    C[(((size_t)b * Hh + h0) * Sq + s) * DhD + d0] = v0;
                    C[(((size_t)b * Hh + h1) * Sq + s) * DhD + d1] = v1;
                } else {
                    v0 = 0.5f * v0 * (1.f + erff(v0 * 0.70710678118654752f));
                    v1 = 0.5f * v1 * (1.f + erff(v1 * 0.70710678118654752f));
                    *(float2*)&C[(size_t)row * N + col] = make_float2(v0, v1);
                }
            }
        }
    }
}

// ---------------- rotary (3-axis) on [B,H,S,Dh] tensor, in place ----------------
__constant__ float c_invfreq[8] = {
    1.0f, 0.31622776601683794f, 0.1f, 0.031622776601683794f,
    0.01f, 0.0031622776601683794f, 0.001f, 0.00031622776601683794f
};

__global__ void rotary_kernel(float* __restrict__ X) {
    int idx = blockIdx.x * blockDim.x + threadIdx.x;   // over B*H*S
    if (idx >= Bz*Hh*Sq) return;
    int s  = idx % Sq;
    int bh = idx / Sq;
    int b  = bh / Hh;
    const float* co = &g_coords[((size_t)b*Sq + s)*3];
    float* x = &X[(size_t)idx * DhD];
    #pragma unroll
    for (int a = 0; a < 3; a++) {
        float coord = co[a];
        #pragma unroll
        for (int j = 0; j < 8; j++) {
            float ang = coord * c_invfreq[j];
            float c, sn;
            __sincosf(ang, &sn, &c);
            float x1 = x[a*16 + j];
            float x2 = x[a*16 + 8 + j];
            x[a*16 + j]     = x1*c - x2*sn;
            x[a*16 + 8 + j] = x1*sn + x2*c;
        }
    }
}

// ---------------- tensor-core flash attention ----------------
// block: 128 queries of one (b,h); 8 warps, warp owns 16 query rows.
// key tiles of 64; QK^T and PV via m16n8k8 tf32.
#define QT 128
#define KT 64
#define SK_STR 52
#define SP_STR 68
// smem (u32): sK 64*52=3328 | sVt 48*68=3264 | sP 128*68=8704  -> 61184 bytes
#define ATT_SM_U32 (3328 + 3264 + 8704)
#define ATT_SM_BYTES (ATT_SM_U32 * 4)

__global__ void __launch_bounds__(256, 2)
attn_mma_kernel() {
    extern __shared__ uint32_t sm[];
    uint32_t* sK  = sm;
    uint32_t* sVt = sm + 3328;
    uint32_t* sP  = sm + 3328 + 3264;
    uint32_t* sQ  = sP;                    // alias (Q staging only at start)

    int bh = blockIdx.y;
    int b = bh >> 3, h = bh & 7;
    int q0 = blockIdx.x * QT;
    int tid = threadIdx.x, lane = tid & 31, w = tid >> 5;
    int g = lane >> 2, t = lane & 3;
    int wl = w * 16;

    const float scale = 0.14433756729740645f;   // 1/sqrt(48)
    const float* Qb = &g_q[(size_t)bh * Sq * DhD];
    const float* Kb = &g_k[(size_t)bh * Sq * DhD];
    const float* Vb = &g_v[(size_t)bh * Sq * DhD];

    // stage Q tile (scaled, tf32) into sQ
    #pragma unroll
    for (int i = 0; i < 6; i++) {
        int e = tid + i * 256;            // 0..1535 ; 128 rows x 12 float4
        int r = e / 12, c4 = e % 12;
        int gr = q0 + r; if (gr >= Sq) gr = Sq - 1;
        float4 v = *(const float4*)&Qb[(size_t)gr * DhD + c4 * 4];
        uint32_t* dst = &sQ[r * SK_STR + c4 * 4];
        dst[0] = f2tf32(v.x * scale); dst[1] = f2tf32(v.y * scale);
        dst[2] = f2tf32(v.z * scale); dst[3] = f2tf32(v.w * scale);
    }
    __syncthreads();

    uint32_t aQ[6][4];
    #pragma unroll
    for (int kk = 0; kk < 6; kk++) {
        int base = (wl + g) * SK_STR + kk * 8 + t;
        aQ[kk][0] = sQ[base];
        aQ[kk][1] = sQ[base + 8 * SK_STR];
        aQ[kk][2] = sQ[base + 4];
        aQ[kk][3] = sQ[base + 8 * SK_STR + 4];
    }
    __syncthreads();   // everyone has Q frags before sP (=sQ) is reused

    int row0 = q0 + wl + g, row1 = row0 + 8;
    int klr0 = (row0 < NM1) ? NM1 : Sq;
    int klr1 = (row1 < NM1) ? NM1 : Sq;

    float m0 = -1e30f, m1 = -1e30f, l0 = 0.f, l1 = 0.f;
    float acc_o[6][4] = {};

    int klmax = (q0 + QT - 1 >= NM1) ? Sq : NM1;
    int nkt = (klmax + KT - 1) / KT;

    for (int kt = 0; kt < nkt; kt++) {
        int kt0 = kt * KT;
        __syncthreads();
        // K tile -> sK (tf32)
        #pragma unroll
        for (int i = 0; i < 3; i++) {
            int e = tid + i * 256;        // 64 rows x 12 float4
            int r = e / 12, c4 = e % 12;
            int gk = kt0 + r; if (gk >= Sq) gk = Sq - 1;
            float4 v = *(const float4*)&Kb[(size_t)gk * DhD + c4 * 4];
            uint32_t* dst = &sK[r * SK_STR + c4 * 4];
            dst[0]=f2tf32(v.x); dst[1]=f2tf32(v.y); dst[2]=f2tf32(v.z); dst[3]=f2tf32(v.w);
        }
        // V tile transposed -> sVt[dh][key] (tf32)
        #pragma unroll
        for (int i = 0; i < 3; i++) {
            int e = tid + i * 256;
            int r = e / 12, c4 = e % 12;
            int gk = kt0 + r; if (gk >= Sq) gk = Sq - 1;
            float4 v = *(const float4*)&Vb[(size_t)gk * DhD + c4 * 4];
            sVt[(c4*4+0) * SP_STR + r] = f2tf32(v.x);
            sVt[(c4*4+1) * SP_STR + r] = f2tf32(v.y);
            sVt[(c4*4+2) * SP_STR + r] = f2tf32(v.z);
            sVt[(c4*4+3) * SP_STR + r] = f2tf32(v.w);
        }
        __syncthreads();

        // scores: S = Q K^T  (warp: 16 rows x 64 keys, 8 ni frags)
        float s[8][4];
        #pragma unroll
        for (int ni = 0; ni < 8; ni++) { s[ni][0]=0.f; s[ni][1]=0.f; s[ni][2]=0.f; s[ni][3]=0.f; }
        #pragma unroll
        for (int kk = 0; kk < 6; kk++) {
            #pragma unroll
            for (int ni = 0; ni < 8; ni++) {
                uint32_t bf[2];
                int bb = (ni * 8 + g) * SK_STR + kk * 8 + t;
                bf[0] = sK[bb]; bf[1] = sK[bb + 4];
                MMA_TF32(s[ni], aQ[kk], bf);
            }
        }

        // mask + row max
        float tm0 = -1e30f, tm1 = -1e30f;
        #pragma unroll
        for (int ni = 0; ni < 8; ni++) {
            int c = kt0 + ni * 8 + 2 * t;
            if (c     >= klr0) s[ni][0] = -1e30f;
            if (c + 1 >= klr0) s[ni][1] = -1e30f;
            if (c     >= klr1) s[ni][2] = -1e30f;
            if (c + 1 >= klr1) s[ni][3] = -1e30f;
            tm0 = fmaxf(tm0, fmaxf(s[ni][0], s[ni][1]));
            tm1 = fmaxf(tm1, fmaxf(s[ni][2], s[ni][3]));
        }
        tm0 = fmaxf(tm0, __shfl_xor_sync(0xffffffffu, tm0, 1));
        tm0 = fmaxf(tm0, __shfl_xor_sync(0xffffffffu, tm0, 2));
        tm1 = fmaxf(tm1, __shfl_xor_sync(0xffffffffu, tm1, 1));
        tm1 = fmaxf(tm1, __shfl_xor_sync(0xffffffffu, tm1, 2));
        float m0n = fmaxf(m0, tm0), m1n = fmaxf(m1, tm1);
        float sf0 = __expf(m0 - m0n), sf1 = __expf(m1 - m1n);
        m0 = m0n; m1 = m1n;

        float sp0 = 0.f, sp1 = 0.f;
        #pragma unroll
        for (int ni = 0; ni < 8; ni++) {
            uint32_t u0 = f2tf32(__expf(s[ni][0] - m0));
            uint32_t u1 = f2tf32(__expf(s[ni][1] - m0));
            uint32_t u2 = f2tf32(__expf(s[ni][2] - m1));
            uint32_t u3 = f2tf32(__expf(s[ni][3] - m1));
            // sum the tf32-rounded values so numerator/denominator agree exactly
            sp0 += __uint_as_float(u0) + __uint_as_float(u1);
            sp1 += __uint_as_float(u2) + __uint_as_float(u3);
            int cl = ni * 8 + 2 * t;
            *(uint2*)&sP[(wl + g)     * SP_STR + cl] = make_uint2(u0, u1);
            *(uint2*)&sP[(wl + g + 8) * SP_STR + cl] = make_uint2(u2, u3);
        }
        sp0 += __shfl_xor_sync(0xffffffffu, sp0, 1);
        sp0 += __shfl_xor_sync(0xffffffffu, sp0, 2);
        sp1 += __shfl_xor_sync(0xffffffffu, sp1, 1);
        sp1 += __shfl_xor_sync(0xffffffffu, sp1, 2);
        l0 = l0 * sf0 + sp0;
        l1 = l1 * sf1 + sp1;
        #pragma unroll
        for (int ni = 0; ni < 6; ni++) {
            acc_o[ni][0] *= sf0; acc_o[ni][1] *= sf0;
            acc_o[ni][2] *= sf1; acc_o[ni][3] *= sf1;
        }
        __syncwarp();

        // O += P V   (warp-local P rows; B = V^T)
        #pragma unroll
        for (int kk = 0; kk < 8; kk++) {
            uint32_t af[4];
            int base = (wl + g) * SP_STR + kk * 8 + t;
            af[0] = sP[base];
            af[1] = sP[base + 8 * SP_STR];
            af[2] = sP[base + 4];
            af[3] = sP[base + 8 * SP_STR + 4];
            #pragma unroll
            for (int ni = 0; ni < 6; ni++) {
                uint32_t bf[2];
                int bb = (ni * 8 + g) * SP_STR + kk * 8 + t;
                bf[0] = sVt[bb]; bf[1] = sVt[bb + 4];
                MMA_TF32(acc_o[ni], af, bf);
            }
        }
    }

    float inv0 = 1.f / l0, inv1 = 1.f / l1;
    #pragma unroll
    for (int ni = 0; ni < 6; ni++) {
        int col = h * DhD + ni * 8 + 2 * t;
        if (row0 < Sq)
            *(float2*)&g_attn[((size_t)b * Sq + row0) * Dd + col] =
                make_float2(acc_o[ni][0] * inv0, acc_o[ni][1] * inv0);
        if (row1 < Sq)
            *(float2*)&g_attn[((size_t)b * Sq + row1) * Dd + col] =
                make_float2(acc_o[ni][2] * inv1, acc_o[ni][3] * inv1);
    }
}

// ---------------- residual + LayerNorm (block per row) ----------------
__global__ void __launch_bounds__(128)
add_ln_kernel(const float* X, const float* Yres, float* Out,
              const float* __restrict__ g, const float* __restrict__ be) {
    int row = blockIdx.x;
    __shared__ float red[128];
    const float* x = X + (size_t)row * Dd;
    const float* y = Yres + (size_t)row * Dd;
    float lx[3];
    float sum = 0.f;
    #pragma unroll
    for (int i = 0; i < 3; i++) {
        int d = threadIdx.x + i*128;
        lx[i] = x[d] + y[d];
        sum += lx[i];
    }
    red[threadIdx.x] = sum; __syncthreads();
    for (int st = 64; st > 0; st >>= 1) {
        if (threadIdx.x < st) red[threadIdx.x] += red[threadIdx.x + st];
        __syncthreads();
    }
    float mean = red[0] * (1.f / Dd);
    __syncthreads();
    float vs = 0.f;
    #pragma unroll
    for (int i = 0; i < 3; i++) { float dd = lx[i] - mean; vs += dd*dd; }
    red[threadIdx.x] = vs; __syncthreads();
    for (int st = 64; st > 0; st >>= 1) {
        if (threadIdx.x < st) red[threadIdx.x] += red[threadIdx.x + st];
        __syncthreads();
    }
    float rstd = rsqrtf(red[0] * (1.f / Dd) + 1e-5f);
    #pragma unroll
    for (int i = 0; i < 3; i++) {
        int d = threadIdx.x + i*128;
        Out[(size_t)row*Dd + d] = (lx[i] - mean) * rstd * g[d] + be[d];
    }
}

// ---------------- final extraction ----------------
__global__ void extract_kernel(float* __restrict__ out) {
    int idx = blockIdx.x * blockDim.x + threadIdx.x;
    if (idx >= Bz*Tt*Dd) return;
    int d  = idx % Dd;
    int bt = idx / Dd;
    int t  = bt % Tt;
    int b  = bt / Tt;
    out[idx] = g_src[((size_t)b*Sq + (Sq - Tt + t))*Dd + d];
}

// ---------------- host launcher ----------------
extern "C" void kernel_launch(void* const* d_in, const int* in_sizes, int n_in,
                              void* d_out, int out_size) {
    const float* hand_t   = (const float*)d_in[0];
    const float* head_t   = (const float*)d_in[1];
    const float* hand_m1  = (const float*)d_in[2];
    const float* head_m1  = (const float*)d_in[3];
    const float* c_hand_t = (const float*)d_in[4];
    const float* c_head_t = (const float*)d_in[5];
    const float* c_hand_m1= (const float*)d_in[6];
    const float* c_head_m1= (const float*)d_in[7];
    const float* state_t  = (const float*)d_in[8];
    const float* state_m1 = (const float*)d_in[9];
    const float* tr_t     = (const float*)d_in[10];
    const float* tr_m1    = (const float*)d_in[11];
    const float* tokens_m1= (const float*)d_in[12];
    const float* tokens_t = (const float*)d_in[13];
    const float* Wq = (const float*)d_in[14];
    const float* bq = (const float*)d_in[15];
    const float* Wk = (const float*)d_in[16];
    const float* bk = (const float*)d_in[17];
    const float* Wv = (const float*)d_in[18];
    const float* bv = (const float*)d_in[19];
    const float* Wo = (const float*)d_in[20];
    const float* bo = (const float*)d_in[21];
    const float* W1 = (const float*)d_in[22];
    const float* b1 = (const float*)d_in[23];
    const float* W2 = (const float*)d_in[24];
    const float* b2 = (const float*)d_in[25];
    const float* g1 = (const float*)d_in[26];
    const float* be1= (const float*)d_in[27];
    const float* g2 = (const float*)d_in[28];
    const float* be2= (const float*)d_in[29];

    float *src, *q, *k, *v, *attn, *tmp, *ff;
    cudaGetSymbolAddress((void**)&src,  g_src);
    cudaGetSymbolAddress((void**)&q,    g_q);
    cudaGetSymbolAddress((void**)&k,    g_k);
    cudaGetSymbolAddress((void**)&v,    g_v);
    cudaGetSymbolAddress((void**)&attn, g_attn);
    cudaGetSymbolAddress((void**)&tmp,  g_tmp);
    cudaGetSymbolAddress((void**)&ff,   g_ff);

    cudaFuncSetAttribute(tf32_mma_gemm, cudaFuncAttributeMaxDynamicSharedMemorySize, GSM_TOTAL);
    cudaFuncSetAttribute(attn_mma_kernel, cudaFuncAttributeMaxDynamicSharedMemorySize, ATT_SM_BYTES);

    build_src_kernel<<<(Mrows*Dd + 255)/256, 256>>>(hand_t, head_t, hand_m1, head_m1,
                                                    state_t, state_m1, tokens_m1, tokens_t);
    build_coords_kernel<<<(Mrows*3 + 255)/256, 256>>>(c_hand_t, c_head_t, c_hand_m1, c_head_m1,
                                                      tr_t, tr_m1);

    dim3 gD(Dd/64,  (Mrows + 127)/128);   // (6, 65)
    dim3 gF(FFd/64, (Mrows + 127)/128);   // (24, 65)
    dim3 gAttn((Sq + QT - 1)/QT, Bz*Hh);  // (9, 64)

    for (int l = 0; l < Ll; l++) {
        const float* wq = Wq + (size_t)l*Dd*Dd;  const float* bql = bq + (size_t)l*Dd;
        const float* wk = Wk + (size_t)l*Dd*Dd;  const float* bkl = bk + (size_t)l*Dd;
        const float* wv = Wv + (size_t)l*Dd*Dd;  const float* bvl = bv + (size_t)l*Dd;
        const float* wo = Wo + (size_t)l*Dd*Dd;  const float* bol = bo + (size_t)l*Dd;
        const float* w1 = W1 + (size_t)l*FFd*Dd; const float* b1l = b1 + (size_t)l*FFd;
        const float* w2 = W2 + (size_t)l*Dd*FFd; const float* b2l = b2 + (size_t)l*Dd;
        const float* g1l = g1 + (size_t)l*Dd;    const float* be1l = be1 + (size_t)l*Dd;
        const float* g2l = g2 + (size_t)l*Dd;    const float* be2l = be2 + (size_t)l*Dd;

        tf32_mma_gemm<<<gD, 256, GSM_TOTAL>>>(src, wq, bql, q, Mrows, Dd, Dd, 1);
        tf32_mma_gemm<<<gD, 256, GSM_TOTAL>>>(src, wk, bkl, k, Mrows, Dd, Dd, 1);
        tf32_mma_gemm<<<gD, 256, GSM_TOTAL>>>(src, wv, bvl, v, Mrows, Dd, Dd, 1);

        rotary_kernel<<<(Bz*Hh*Sq + 127)/128, 128>>>(q);
        rotary_kernel<<<(Bz*Hh*Sq + 127)/128, 128>>>(k);

        attn_mma_kernel<<<gAttn, 256, ATT_SM_BYTES>>>();

        tf32_mma_gemm<<<gD, 256, GSM_TOTAL>>>(attn, wo, bol, tmp, Mrows, Dd, Dd, 0);
        add_ln_kernel<<<Mrows, 128>>>(src, tmp, src, g1l, be1l);

        tf32_mma_gemm<<<gF, 256, GSM_TOTAL>>>(src, w1, b1l, ff, Mrows, FFd, Dd, 2);
        tf32_mma_gemm<<<gD, 256, GSM_TOTAL>>>(ff, w2, b2l, tmp, Mrows, Dd, FFd, 0);
        add_ln_kernel<<<Mrows, 128>>>(src, tmp, src, g2l, be2l);
    }

    extract_kernel<<<(Bz*Tt*Dd + 255)/256, 256>>>((float*)d_out);
}

// round 5
// speedup vs baseline: 2.8542x; 1.3085x over previous
#include <cuda_runtime.h>
#include <cstdint>
#include <math.h>

// ---------------- problem constants ----------------
#define Bz   8
#define Nn   256
#define Dd   384
#define Ll   6
#define Hh   8
#define FFd  1536
#define Tt   4
#define DhD  48
#define NM1  517            // T + 1 + 2N
#define Sq   1034           // 2*NM1
#define Mrows (Bz*Sq)       // 8272

// ---------------- device scratch ----------------
__device__ float g_src   [Mrows*Dd];
__device__ float g_coords[Mrows*3];
__device__ float g_q     [Mrows*Dd];
__device__ float g_k     [Mrows*Dd];
__device__ float g_v     [Mrows*Dd];
__device__ float g_attn  [Mrows*Dd];
__device__ float g_tmp   [Mrows*Dd];
__device__ float g_ff    [Mrows*FFd];

// ---------------- build src / coords ----------------
__global__ void build_src_kernel(const float* __restrict__ hand_t, const float* __restrict__ head_t,
                                 const float* __restrict__ hand_m1, const float* __restrict__ head_m1,
                                 const float* __restrict__ state_t, const float* __restrict__ state_m1,
                                 const float* __restrict__ tok_m1, const float* __restrict__ tok_t) {
    int idx = blockIdx.x * blockDim.x + threadIdx.x;
    if (idx >= Mrows * Dd) return;
    int d  = idx % Dd;
    int bs = idx / Dd;
    int s  = bs % Sq;
    int b  = bs / Sq;
    int half = (s >= NM1) ? 1 : 0;
    int sl = s - half * NM1;
    float v;
    if (sl == 0)            v = (half ? state_t : state_m1)[b*Dd + d];
    else if (sl <= Nn)      v = (half ? hand_t : hand_m1)[(b*Nn + sl-1)*Dd + d];
    else if (sl <= 2*Nn)    v = (half ? head_t : head_m1)[(b*Nn + sl-1-Nn)*Dd + d];
    else                    v = (half ? tok_t : tok_m1)[(sl-1-2*Nn)*Dd + d];
    g_src[idx] = v;
}

__global__ void build_coords_kernel(const float* __restrict__ ch_t, const float* __restrict__ chd_t,
                                    const float* __restrict__ ch_m1, const float* __restrict__ chd_m1,
                                    const float* __restrict__ tr_t, const float* __restrict__ tr_m1) {
    int idx = blockIdx.x * blockDim.x + threadIdx.x;
    if (idx >= Mrows * 3) return;
    int c  = idx % 3;
    int bs = idx / 3;
    int s  = bs % Sq;
    int b  = bs / Sq;
    int half = (s >= NM1) ? 1 : 0;
    int sl = s - half * NM1;
    float v;
    if (sl == 0 || sl > 2*Nn) v = (half ? tr_t : tr_m1)[b*3 + c];
    else if (sl <= Nn)        v = (half ? ch_t : ch_m1)[(b*Nn + sl-1)*3 + c];
    else                      v = (half ? chd_t : chd_m1)[(b*Nn + sl-1-Nn)*3 + c];
    g_coords[idx] = v;
}

// ---------------- mma / cp.async helpers ----------------
__device__ __forceinline__ uint32_t f2tf32(float f) {
    uint32_t u;
    asm("cvt.rna.tf32.f32 %0, %1;" : "=r"(u) : "f"(f));
    return u;
}
__device__ __forceinline__ uint32_t smem_u32(const void* p) {
    uint32_t a;
    asm("{ .reg .u64 t; cvta.to.shared.u64 t, %1; cvt.u32.u64 %0, t; }" : "=r"(a) : "l"(p));
    return a;
}

#define MMA_TF32(d, a, b) \
    asm("mma.sync.aligned.m16n8k8.row.col.f32.tf32.tf32.f32 " \
        "{%0,%1,%2,%3}, {%4,%5,%6,%7}, {%8,%9}, {%0,%1,%2,%3};" \
        : "+f"((d)[0]), "+f"((d)[1]), "+f"((d)[2]), "+f"((d)[3]) \
        : "r"((a)[0]), "r"((a)[1]), "r"((a)[2]), "r"((a)[3]), \
          "r"((b)[0]), "r"((b)[1]))

#define CPA16(dst, src) \
    asm volatile("cp.async.cg.shared.global [%0], [%1], 16;" :: "r"(dst), "l"(src) : "memory")
#define CPCOMMIT() asm volatile("cp.async.commit_group;" ::: "memory")
#define CPWAIT0()  asm volatile("cp.async.wait_group 0;" ::: "memory")
#define CPWAIT1()  asm volatile("cp.async.wait_group 1;" ::: "memory")

// ---------------- tf32 mma GEMM with cp.async 3-stage pipeline ----------------
// C = A(M,K) * W(N,K)^T + bias ; tile 128x64x32, 256 thr (8 warps 4x2), warp 32x32.
#define PAD_STR 36                            // floats per smem row (32 + 4 pad)
#define SA_FLOATS (128 * PAD_STR)             // 4608
#define SB_FLOATS (64 * PAD_STR)              // 2304
#define STAGE_FLOATS (SA_FLOATS + SB_FLOATS)  // 6912
#define STAGE_BYTES (STAGE_FLOATS * 4)
#define GSM_TOTAL (3 * STAGE_BYTES)           // 82944

__device__ __forceinline__ void cp_chunk(const float* __restrict__ A, const float* __restrict__ W,
                                         int M, int K, int m0, int n0, int k0, uint32_t sStage) {
    int tid = threadIdx.x;
    uint32_t sA = sStage;
    uint32_t sB = sStage + SA_FLOATS * 4;
    #pragma unroll
    for (int i = 0; i < 4; i++) {                 // A: 128x32 = 1024 x 16B
        int e = tid + i * 256;
        int r = e >> 3, c4 = e & 7;
        int gm = m0 + r; if (gm > M - 1) gm = M - 1;
        CPA16(sA + (uint32_t)(r * PAD_STR + c4 * 4) * 4, A + (size_t)gm * K + k0 + c4 * 4);
    }
    #pragma unroll
    for (int i = 0; i < 2; i++) {                 // B: 64x32 = 512 x 16B
        int e = tid + i * 256;
        int r = e >> 3, c4 = e & 7;
        CPA16(sB + (uint32_t)(r * PAD_STR + c4 * 4) * 4, W + (size_t)(n0 + r) * K + k0 + c4 * 4);
    }
}

// mainloop: fills acc[2][4][4] for this block's 128x64 tile
__device__ __forceinline__ void gemm_main(const float* __restrict__ A, const float* __restrict__ W,
                                          int M, int K, int m0, int n0,
                                          uint32_t* smu, uint32_t sbase, float acc[2][4][4]) {
    int NC = K / 32;
    int lane = threadIdx.x & 31, wid = threadIdx.x >> 5;
    int wm = wid & 3, wn = wid >> 2;
    int g = lane >> 2, t = lane & 3;

    cp_chunk(A, W, M, K, m0, n0, 0, sbase);              CPCOMMIT();
    cp_chunk(A, W, M, K, m0, n0, 32, sbase + STAGE_BYTES); CPCOMMIT();

    for (int c = 0; c < NC; c++) {
        if (c + 1 < NC) { CPWAIT1(); } else { CPWAIT0(); }
        __syncthreads();
        if (c + 2 < NC) {
            int st = (c + 2) % 3;
            cp_chunk(A, W, M, K, m0, n0, (c + 2) * 32, sbase + st * STAGE_BYTES);
            CPCOMMIT();
        }
        const uint32_t* cA = smu + (c % 3) * STAGE_FLOATS;
        const uint32_t* cB = cA + SA_FLOATS;

        #pragma unroll
        for (int kk = 0; kk < 4; kk++) {
            uint32_t af[2][4], bf[4][2];
            #pragma unroll
            for (int mi = 0; mi < 2; mi++) {
                int base = (wm * 32 + mi * 16 + g) * PAD_STR + kk * 8 + t;
                af[mi][0] = cA[base];
                af[mi][1] = cA[base + 8 * PAD_STR];
                af[mi][2] = cA[base + 4];
                af[mi][3] = cA[base + 8 * PAD_STR + 4];
            }
            #pragma unroll
            for (int ni = 0; ni < 4; ni++) {
                int bb = (wn * 32 + ni * 8 + g) * PAD_STR + kk * 8 + t;
                bf[ni][0] = cB[bb];
                bf[ni][1] = cB[bb + 4];
            }
            #pragma unroll
            for (int mi = 0; mi < 2; mi++)
                #pragma unroll
                for (int ni = 0; ni < 4; ni++)
                    MMA_TF32(acc[mi][ni], af[mi], bf[ni]);
        }
    }
}

// generic GEMM kernel: mode 0 = plain + bias, mode 2 = exact GELU
__global__ void __launch_bounds__(256, 2)
gemm_cp(const float* __restrict__ A, const float* __restrict__ W,
        const float* __restrict__ bias, float* __restrict__ C,
        int M, int N, int K, int mode) {
    extern __shared__ uint32_t smu[];
    uint32_t sbase = smem_u32(smu);
    int lane = threadIdx.x & 31, wid = threadIdx.x >> 5;
    int wm = wid & 3, wn = wid >> 2;
    int g = lane >> 2, t = lane & 3;
    int m0 = blockIdx.y * 128, n0 = blockIdx.x * 64;

    float acc[2][4][4] = {};
    gemm_main(A, W, M, K, m0, n0, smu, sbase, acc);

    #pragma unroll
    for (int mi = 0; mi < 2; mi++) {
        #pragma unroll
        for (int half = 0; half < 2; half++) {
            int row = m0 + wm * 32 + mi * 16 + g + half * 8;
            if (row >= M) continue;
            #pragma unroll
            for (int ni = 0; ni < 4; ni++) {
                int col = n0 + wn * 32 + ni * 8 + 2 * t;
                float v0 = acc[mi][ni][half * 2 + 0] + bias[col];
                float v1 = acc[mi][ni][half * 2 + 1] + bias[col + 1];
                if (mode == 2) {
                    v0 = 0.5f * v0 * (1.f + erff(v0 * 0.70710678118654752f));
                    v1 = 0.5f * v1 * (1.f + erff(v1 * 0.70710678118654752f));
                }
                *(float2*)&C[(size_t)row * N + col] = make_float2(v0, v1);
            }
        }
    }
}

// fused QKV kernel: grid.x = 18 (3 outputs x 6 col-tiles); writes head layout [B,H,S,Dh]
__global__ void __launch_bounds__(256, 2)
qkv_gemm_cp(const float* __restrict__ A,
            const float* __restrict__ wq, const float* __restrict__ wk, const float* __restrict__ wv,
            const float* __restrict__ bq, const float* __restrict__ bk, const float* __restrict__ bv,
            float* __restrict__ q, float* __restrict__ k, float* __restrict__ v) {
    extern __shared__ uint32_t smu[];
    uint32_t sbase = smem_u32(smu);
    int sel = blockIdx.x / 6;
    int n0 = (blockIdx.x % 6) * 64;
    const float* W    = (sel == 0) ? wq : (sel == 1) ? wk : wv;
    const float* bias = (sel == 0) ? bq : (sel == 1) ? bk : bv;
    float* C          = (sel == 0) ? q  : (sel == 1) ? k  : v;

    int lane = threadIdx.x & 31, wid = threadIdx.x >> 5;
    int wm = wid & 3, wn = wid >> 2;
    int g = lane >> 2, t = lane & 3;
    int m0 = blockIdx.y * 128;

    float acc[2][4][4] = {};
    gemm_main(A, W, Mrows, Dd, m0, n0, smu, sbase, acc);

    #pragma unroll
    for (int mi = 0; mi < 2; mi++) {
        #pragma unroll
        for (int half = 0; half < 2; half++) {
            int row = m0 + wm * 32 + mi * 16 + g + half * 8;
            if (row >= Mrows) continue;
            int b = row / Sq, s = row % Sq;
            #pragma unroll
            for (int ni = 0; ni < 4; ni++) {
                int col = n0 + wn * 32 + ni * 8 + 2 * t;
                float v0 = acc[mi][ni][half * 2 + 0] + bias[col];
                float v1 = acc[mi][ni][half * 2 + 1] + bias[col + 1];
                int h0 = col / DhD, d0 = col % DhD;
                int h1 = (col + 1) / DhD, d1 = (col + 1) % DhD;
                C[(((size_t)b * Hh + h0) * Sq + s) * DhD + d0] = v0;
                C[(((size_t)b * Hh + h1) * Sq + s) * DhD + d1] = v1;
            }
        }
    }
}

// ---------------- rotary (3-axis), q and k in one launch ----------------
__constant__ float c_invfreq[8] = {
    1.0f, 0.31622776601683794f, 0.1f, 0.031622776601683794f,
    0.01f, 0.0031622776601683794f, 0.001f, 0.00031622776601683794f
};

__global__ void rotary_kernel(float* __restrict__ Q, float* __restrict__ K) {
    int idx = blockIdx.x * blockDim.x + threadIdx.x;   // over 2*B*H*S
    if (idx >= 2*Bz*Hh*Sq) return;
    float* X = (idx < Bz*Hh*Sq) ? Q : K;
    int id = (idx < Bz*Hh*Sq) ? idx : idx - Bz*Hh*Sq;
    int s  = id % Sq;
    int bh = id / Sq;
    int b  = bh / Hh;
    const float* co = &g_coords[((size_t)b*Sq + s)*3];
    float* x = &X[(size_t)id * DhD];
    #pragma unroll
    for (int a = 0; a < 3; a++) {
        float coord = co[a];
        #pragma unroll
        for (int j = 0; j < 8; j++) {
            float ang = coord * c_invfreq[j];
            float c, sn;
            __sincosf(ang, &sn, &c);
            float x1 = x[a*16 + j];
            float x2 = x[a*16 + 8 + j];
            x[a*16 + j]     = x1*c - x2*sn;
            x[a*16 + 8 + j] = x1*sn + x2*c;
        }
    }
}

// ---------------- tensor-core flash attention ----------------
#define QT 128
#define KT 64
#define SK_STR 52
#define SP_STR 68
#define ATT_SM_U32 (3328 + 3264 + 8704)
#define ATT_SM_BYTES (ATT_SM_U32 * 4)

__global__ void __launch_bounds__(256, 2)
attn_mma_kernel() {
    extern __shared__ uint32_t sm[];
    uint32_t* sK  = sm;
    uint32_t* sVt = sm + 3328;
    uint32_t* sP  = sm + 3328 + 3264;
    uint32_t* sQ  = sP;

    int bh = blockIdx.y;
    int b = bh >> 3, h = bh & 7;
    int q0 = blockIdx.x * QT;
    int tid = threadIdx.x, lane = tid & 31, w = tid >> 5;
    int g = lane >> 2, t = lane & 3;
    int wl = w * 16;

    const float scale = 0.14433756729740645f;
    const float* Qb = &g_q[(size_t)bh * Sq * DhD];
    const float* Kb = &g_k[(size_t)bh * Sq * DhD];
    const float* Vb = &g_v[(size_t)bh * Sq * DhD];

    #pragma unroll
    for (int i = 0; i < 6; i++) {
        int e = tid + i * 256;
        int r = e / 12, c4 = e % 12;
        int gr = q0 + r; if (gr >= Sq) gr = Sq - 1;
        float4 v = *(const float4*)&Qb[(size_t)gr * DhD + c4 * 4];
        uint32_t* dst = &sQ[r * SK_STR + c4 * 4];
        dst[0] = f2tf32(v.x * scale); dst[1] = f2tf32(v.y * scale);
        dst[2] = f2tf32(v.z * scale); dst[3] = f2tf32(v.w * scale);
    }
    __syncthreads();

    uint32_t aQ[6][4];
    #pragma unroll
    for (int kk = 0; kk < 6; kk++) {
        int base = (wl + g) * SK_STR + kk * 8 + t;
        aQ[kk][0] = sQ[base];
        aQ[kk][1] = sQ[base + 8 * SK_STR];
        aQ[kk][2] = sQ[base + 4];
        aQ[kk][3] = sQ[base + 8 * SK_STR + 4];
    }
    __syncthreads();

    int row0 = q0 + wl + g, row1 = row0 + 8;
    int klr0 = (row0 < NM1) ? NM1 : Sq;
    int klr1 = (row1 < NM1) ? NM1 : Sq;

    float m0 = -1e30f, m1 = -1e30f, l0 = 0.f, l1 = 0.f;
    float acc_o[6][4] = {};

    int klmax = (q0 + QT - 1 >= NM1) ? Sq : NM1;
    int nkt = (klmax + KT - 1) / KT;

    for (int kt = 0; kt < nkt; kt++) {
        int kt0 = kt * KT;
        __syncthreads();
        #pragma unroll
        for (int i = 0; i < 3; i++) {
            int e = tid + i * 256;
            int r = e / 12, c4 = e % 12;
            int gk = kt0 + r; if (gk >= Sq) gk = Sq - 1;
            float4 v = *(const float4*)&Kb[(size_t)gk * DhD + c4 * 4];
            uint32_t* dst = &sK[r * SK_STR + c4 * 4];
            dst[0]=f2tf32(v.x); dst[1]=f2tf32(v.y); dst[2]=f2tf32(v.z); dst[3]=f2tf32(v.w);
        }
        #pragma unroll
        for (int i = 0; i < 3; i++) {
            int e = tid + i * 256;
            int r = e / 12, c4 = e % 12;
            int gk = kt0 + r; if (gk >= Sq) gk = Sq - 1;
            float4 v = *(const float4*)&Vb[(size_t)gk * DhD + c4 * 4];
            sVt[(c4*4+0) * SP_STR + r] = f2tf32(v.x);
            sVt[(c4*4+1) * SP_STR + r] = f2tf32(v.y);
            sVt[(c4*4+2) * SP_STR + r] = f2tf32(v.z);
            sVt[(c4*4+3) * SP_STR + r] = f2tf32(v.w);
        }
        __syncthreads();

        float s[8][4];
        #pragma unroll
        for (int ni = 0; ni < 8; ni++) { s[ni][0]=0.f; s[ni][1]=0.f; s[ni][2]=0.f; s[ni][3]=0.f; }
        #pragma unroll
        for (int kk = 0; kk < 6; kk++) {
            #pragma unroll
            for (int ni = 0; ni < 8; ni++) {
                uint32_t bf[2];
                int bb = (ni * 8 + g) * SK_STR + kk * 8 + t;
                bf[0] = sK[bb]; bf[1] = sK[bb + 4];
                MMA_TF32(s[ni], aQ[kk], bf);
            }
        }

        float tm0 = -1e30f, tm1 = -1e30f;
        #pragma unroll
        for (int ni = 0; ni < 8; ni++) {
            int c = kt0 + ni * 8 + 2 * t;
            if (c     >= klr0) s[ni][0] = -1e30f;
            if (c + 1 >= klr0) s[ni][1] = -1e30f;
            if (c     >= klr1) s[ni][2] = -1e30f;
            if (c + 1 >= klr1) s[ni][3] = -1e30f;
            tm0 = fmaxf(tm0, fmaxf(s[ni][0], s[ni][1]));
            tm1 = fmaxf(tm1, fmaxf(s[ni][2], s[ni][3]));
        }
        tm0 = fmaxf(tm0, __shfl_xor_sync(0xffffffffu, tm0, 1));
        tm0 = fmaxf(tm0, __shfl_xor_sync(0xffffffffu, tm0, 2));
        tm1 = fmaxf(tm1, __shfl_xor_sync(0xffffffffu, tm1, 1));
        tm1 = fmaxf(tm1, __shfl_xor_sync(0xffffffffu, tm1, 2));
        float m0n = fmaxf(m0, tm0), m1n = fmaxf(m1, tm1);
        float sf0 = __expf(m0 - m0n), sf1 = __expf(m1 - m1n);
        m0 = m0n; m1 = m1n;

        float sp0 = 0.f, sp1 = 0.f;
        #pragma unroll
        for (int ni = 0; ni < 8; ni++) {
            uint32_t u0 = f2tf32(__expf(s[ni][0] - m0));
            uint32_t u1 = f2tf32(__expf(s[ni][1] - m0));
            uint32_t u2 = f2tf32(__expf(s[ni][2] - m1));
            uint32_t u3 = f2tf32(__expf(s[ni][3] - m1));
            sp0 += __uint_as_float(u0) + __uint_as_float(u1);
            sp1 += __uint_as_float(u2) + __uint_as_float(u3);
            int cl = ni * 8 + 2 * t;
            *(uint2*)&sP[(wl + g)     * SP_STR + cl] = make_uint2(u0, u1);
            *(uint2*)&sP[(wl + g + 8) * SP_STR + cl] = make_uint2(u2, u3);
        }
        sp0 += __shfl_xor_sync(0xffffffffu, sp0, 1);
        sp0 += __shfl_xor_sync(0xffffffffu, sp0, 2);
        sp1 += __shfl_xor_sync(0xffffffffu, sp1, 1);
        sp1 += __shfl_xor_sync(0xffffffffu, sp1, 2);
        l0 = l0 * sf0 + sp0;
        l1 = l1 * sf1 + sp1;
        #pragma unroll
        for (int ni = 0; ni < 6; ni++) {
            acc_o[ni][0] *= sf0; acc_o[ni][1] *= sf0;
            acc_o[ni][2] *= sf1; acc_o[ni][3] *= sf1;
        }
        __syncwarp();

        #pragma unroll
        for (int kk = 0; kk < 8; kk++) {
            uint32_t af[4];
            int base = (wl + g) * SP_STR + kk * 8 + t;
            af[0] = sP[base];
            af[1] = sP[base + 8 * SP_STR];
            af[2] = sP[base + 4];
            af[3] = sP[base + 8 * SP_STR + 4];
            #pragma unroll
            for (int ni = 0; ni < 6; ni++) {
                uint32_t bf[2];
                int bb = (ni * 8 + g) * SP_STR + kk * 8 + t;
                bf[0] = sVt[bb]; bf[1] = sVt[bb + 4];
                MMA_TF32(acc_o[ni], af, bf);
            }
        }
    }

    float inv0 = 1.f / l0, inv1 = 1.f / l1;
    #pragma unroll
    for (int ni = 0; ni < 6; ni++) {
        int col = h * DhD + ni * 8 + 2 * t;
        if (row0 < Sq)
            *(float2*)&g_attn[((size_t)b * Sq + row0) * Dd + col] =
                make_float2(acc_o[ni][0] * inv0, acc_o[ni][1] * inv0);
        if (row1 < Sq)
            *(float2*)&g_attn[((size_t)b * Sq + row1) * Dd + col] =
                make_float2(acc_o[ni][2] * inv1, acc_o[ni][3] * inv1);
    }
}

// ---------------- residual + LayerNorm (block per row) ----------------
__global__ void __launch_bounds__(128)
add_ln_kernel(const float* X, const float* Yres, float* Out,
              const float* __restrict__ g, const float* __restrict__ be) {
    int row = blockIdx.x;
    __shared__ float red[128];
    const float* x = X + (size_t)row * Dd;
    const float* y = Yres + (size_t)row * Dd;
    float lx[3];
    float sum = 0.f;
    #pragma unroll
    for (int i = 0; i < 3; i++) {
        int d = threadIdx.x + i*128;
        lx[i] = x[d] + y[d];
        sum += lx[i];
    }
    red[threadIdx.x] = sum; __syncthreads();
    for (int st = 64; st > 0; st >>= 1) {
        if (threadIdx.x < st) red[threadIdx.x] += red[threadIdx.x + st];
        __syncthreads();
    }
    float mean = red[0] * (1.f / Dd);
    __syncthreads();
    float vs = 0.f;
    #pragma unroll
    for (int i = 0; i < 3; i++) { float dd = lx[i] - mean; vs += dd*dd; }
    red[threadIdx.x] = vs; __syncthreads();
    for (int st = 64; st > 0; st >>= 1) {
        if (threadIdx.x < st) red[threadIdx.x] += red[threadIdx.x + st];
        __syncthreads();
    }
    float rstd = rsqrtf(red[0] * (1.f / Dd) + 1e-5f);
    #pragma unroll
    for (int i = 0; i < 3; i++) {
        int d = threadIdx.x + i*128;
        Out[(size_t)row*Dd + d] = (lx[i] - mean) * rstd * g[d] + be[d];
    }
}

// ---------------- final extraction ----------------
__global__ void extract_kernel(float* __restrict__ out) {
    int idx = blockIdx.x * blockDim.x + threadIdx.x;
    if (idx >= Bz*Tt*Dd) return;
    int d  = idx % Dd;
    int bt = idx / Dd;
    int t  = bt % Tt;
    int b  = bt / Tt;
    out[idx] = g_src[((size_t)b*Sq + (Sq - Tt + t))*Dd + d];
}

// ---------------- host launcher ----------------
extern "C" void kernel_launch(void* const* d_in, const int* in_sizes, int n_in,
                              void* d_out, int out_size) {
    const float* hand_t   = (const float*)d_in[0];
    const float* head_t   = (const float*)d_in[1];
    const float* hand_m1  = (const float*)d_in[2];
    const float* head_m1  = (const float*)d_in[3];
    const float* c_hand_t = (const float*)d_in[4];
    const float* c_head_t = (const float*)d_in[5];
    const float* c_hand_m1= (const float*)d_in[6];
    const float* c_head_m1= (const float*)d_in[7];
    const float* state_t  = (const float*)d_in[8];
    const float* state_m1 = (const float*)d_in[9];
    const float* tr_t     = (const float*)d_in[10];
    const float* tr_m1    = (const float*)d_in[11];
    const float* tokens_m1= (const float*)d_in[12];
    const float* tokens_t = (const float*)d_in[13];
    const float* Wq = (const float*)d_in[14];
    const float* bq = (const float*)d_in[15];
    const float* Wk = (const float*)d_in[16];
    const float* bk = (const float*)d_in[17];
    const float* Wv = (const float*)d_in[18];
    const float* bv = (const float*)d_in[19];
    const float* Wo = (const float*)d_in[20];
    const float* bo = (const float*)d_in[21];
    const float* W1 = (const float*)d_in[22];
    const float* b1 = (const float*)d_in[23];
    const float* W2 = (const float*)d_in[24];
    const float* b2 = (const float*)d_in[25];
    const float* g1 = (const float*)d_in[26];
    const float* be1= (const float*)d_in[27];
    const float* g2 = (const float*)d_in[28];
    const float* be2= (const float*)d_in[29];

    float *src, *q, *k, *v, *attn, *tmp, *ff;
    cudaGetSymbolAddress((void**)&src,  g_src);
    cudaGetSymbolAddress((void**)&q,    g_q);
    cudaGetSymbolAddress((void**)&k,    g_k);
    cudaGetSymbolAddress((void**)&v,    g_v);
    cudaGetSymbolAddress((void**)&attn, g_attn);
    cudaGetSymbolAddress((void**)&tmp,  g_tmp);
    cudaGetSymbolAddress((void**)&ff,   g_ff);

    cudaFuncSetAttribute(gemm_cp,     cudaFuncAttributeMaxDynamicSharedMemorySize, GSM_TOTAL);
    cudaFuncSetAttribute(qkv_gemm_cp, cudaFuncAttributeMaxDynamicSharedMemorySize, GSM_TOTAL);
    cudaFuncSetAttribute(attn_mma_kernel, cudaFuncAttributeMaxDynamicSharedMemorySize, ATT_SM_BYTES);

    build_src_kernel<<<(Mrows*Dd + 255)/256, 256>>>(hand_t, head_t, hand_m1, head_m1,
                                                    state_t, state_m1, tokens_m1, tokens_t);
    build_coords_kernel<<<(Mrows*3 + 255)/256, 256>>>(c_hand_t, c_head_t, c_hand_m1, c_head_m1,
                                                      tr_t, tr_m1);

    dim3 gQKV(18, (Mrows + 127)/128);    // (18, 65)
    dim3 gD(Dd/64,  (Mrows + 127)/128);  // (6, 65)
    dim3 gF(FFd/64, (Mrows + 127)/128);  // (24, 65)
    dim3 gAttn((Sq + QT - 1)/QT, Bz*Hh); // (9, 64)

    for (int l = 0; l < Ll; l++) {
        const float* wq = Wq + (size_t)l*Dd*Dd;  const float* bql = bq + (size_t)l*Dd;
        const float* wk = Wk + (size_t)l*Dd*Dd;  const float* bkl = bk + (size_t)l*Dd;
        const float* wv = Wv + (size_t)l*Dd*Dd;  const float* bvl = bv + (size_t)l*Dd;
        const float* wo = Wo + (size_t)l*Dd*Dd;  const float* bol = bo + (size_t)l*Dd;
        const float* w1 = W1 + (size_t)l*FFd*Dd; const float* b1l = b1 + (size_t)l*FFd;
        const float* w2 = W2 + (size_t)l*Dd*FFd; const float* b2l = b2 + (size_t)l*Dd;
        const float* g1l = g1 + (size_t)l*Dd;    const float* be1l = be1 + (size_t)l*Dd;
        const float* g2l = g2 + (size_t)l*Dd;    const float* be2l = be2 + (size_t)l*Dd;

        qkv_gemm_cp<<<gQKV, 256, GSM_TOTAL>>>(src, wq, wk, wv, bql, bkl, bvl, q, k, v);

        rotary_kernel<<<(2*Bz*Hh*Sq + 127)/128, 128>>>(q, k);

        attn_mma_kernel<<<gAttn, 256, ATT_SM_BYTES>>>();

        gemm_cp<<<gD, 256, GSM_TOTAL>>>(attn, wo, bol, tmp, Mrows, Dd, Dd, 0);
        add_ln_kernel<<<Mrows, 128>>>(src, tmp, src, g1l, be1l);

        gemm_cp<<<gF, 256, GSM_TOTAL>>>(src, w1, b1l, ff, Mrows, FFd, Dd, 2);
        gemm_cp<<<gD, 256, GSM_TOTAL>>>(ff, w2, b2l, tmp, Mrows, Dd, FFd, 0);
        add_ln_kernel<<<Mrows, 128>>>(src, tmp, src, g2l, be2l);
    }

    extract_kernel<<<(Bz*Tt*Dd + 255)/256, 256>>>((float*)d_out);
}

// round 6
// speedup vs baseline: 3.1585x; 1.1066x over previous
#include <cuda_runtime.h>
#include <cstdint>
#include <math.h>

// ---------------- problem constants ----------------
#define Bz   8
#define Nn   256
#define Dd   384
#define Ll   6
#define Hh   8
#define FFd  1536
#define Tt   4
#define DhD  48
#define NM1  517            // T + 1 + 2N
#define Sq   1034           // 2*NM1
#define Mrows (Bz*Sq)       // 8272

// ---------------- device scratch ----------------
__device__ float g_src   [Mrows*Dd];
__device__ float g_coords[Mrows*3];
__device__ float g_q     [Mrows*Dd];
__device__ float g_k     [Mrows*Dd];
__device__ float g_v     [Mrows*Dd];
__device__ float g_attn  [Mrows*Dd];
__device__ float g_tmp   [Mrows*Dd];
__device__ float g_ff    [Mrows*FFd];
// rounded weights: wq|wk|wv|wo (4 * L*D*D) then w1 (L*FF*D) then w2 (L*D*FF)
#define WSZ_P  (Ll*Dd*Dd)        // 884736
#define WSZ_F  (Ll*FFd*Dd)       // 3538944
__device__ float g_wbuf [4*WSZ_P + 2*WSZ_F];

// ---------------- mma / cp.async helpers ----------------
__device__ __forceinline__ uint32_t f2tf32(float f) {
    uint32_t u;
    asm("cvt.rna.tf32.f32 %0, %1;" : "=r"(u) : "f"(f));
    return u;
}
__device__ __forceinline__ float rnd_tf32(float f) { return __uint_as_float(f2tf32(f)); }
__device__ __forceinline__ uint32_t smem_u32(const void* p) {
    uint32_t a;
    asm("{ .reg .u64 t; cvta.to.shared.u64 t, %1; cvt.u32.u64 %0, t; }" : "=r"(a) : "l"(p));
    return a;
}

#define MMA_TF32(d, a, b) \
    asm("mma.sync.aligned.m16n8k8.row.col.f32.tf32.tf32.f32 " \
        "{%0,%1,%2,%3}, {%4,%5,%6,%7}, {%8,%9}, {%0,%1,%2,%3};" \
        : "+f"((d)[0]), "+f"((d)[1]), "+f"((d)[2]), "+f"((d)[3]) \
        : "r"((a)[0]), "r"((a)[1]), "r"((a)[2]), "r"((a)[3]), \
          "r"((b)[0]), "r"((b)[1]))

#define CPA16(dst, src) \
    asm volatile("cp.async.cg.shared.global [%0], [%1], 16;" :: "r"(dst), "l"(src) : "memory")
#define CPCOMMIT() asm volatile("cp.async.commit_group;" ::: "memory")
#define CPWAIT0()  asm volatile("cp.async.wait_group 0;" ::: "memory")
#define CPWAIT1()  asm volatile("cp.async.wait_group 1;" ::: "memory")

__constant__ float c_invfreq[8] = {
    1.0f, 0.31622776601683794f, 0.1f, 0.031622776601683794f,
    0.01f, 0.0031622776601683794f, 0.001f, 0.00031622776601683794f
};

// ---------------- weight pre-rounding (once per launch) ----------------
__global__ void round_w_kernel(const float4* __restrict__ in, float4* __restrict__ out, int n4) {
    int i = blockIdx.x * blockDim.x + threadIdx.x;
    if (i >= n4) return;
    float4 v = in[i];
    v.x = rnd_tf32(v.x); v.y = rnd_tf32(v.y);
    v.z = rnd_tf32(v.z); v.w = rnd_tf32(v.w);
    out[i] = v;
}

// ---------------- build src / coords ----------------
__global__ void build_src_kernel(const float* __restrict__ hand_t, const float* __restrict__ head_t,
                                 const float* __restrict__ hand_m1, const float* __restrict__ head_m1,
                                 const float* __restrict__ state_t, const float* __restrict__ state_m1,
                                 const float* __restrict__ tok_m1, const float* __restrict__ tok_t) {
    int idx = blockIdx.x * blockDim.x + threadIdx.x;
    if (idx >= Mrows * Dd) return;
    int d  = idx % Dd;
    int bs = idx / Dd;
    int s  = bs % Sq;
    int b  = bs / Sq;
    int half = (s >= NM1) ? 1 : 0;
    int sl = s - half * NM1;
    float v;
    if (sl == 0)            v = (half ? state_t : state_m1)[b*Dd + d];
    else if (sl <= Nn)      v = (half ? hand_t : hand_m1)[(b*Nn + sl-1)*Dd + d];
    else if (sl <= 2*Nn)    v = (half ? head_t : head_m1)[(b*Nn + sl-1-Nn)*Dd + d];
    else                    v = (half ? tok_t : tok_m1)[(sl-1-2*Nn)*Dd + d];
    g_src[idx] = rnd_tf32(v);
}

__global__ void build_coords_kernel(const float* __restrict__ ch_t, const float* __restrict__ chd_t,
                                    const float* __restrict__ ch_m1, const float* __restrict__ chd_m1,
                                    const float* __restrict__ tr_t, const float* __restrict__ tr_m1) {
    int idx = blockIdx.x * blockDim.x + threadIdx.x;
    if (idx >= Mrows * 3) return;
    int c  = idx % 3;
    int bs = idx / 3;
    int s  = bs % Sq;
    int b  = bs / Sq;
    int half = (s >= NM1) ? 1 : 0;
    int sl = s - half * NM1;
    float v;
    if (sl == 0 || sl > 2*Nn) v = (half ? tr_t : tr_m1)[b*3 + c];
    else if (sl <= Nn)        v = (half ? ch_t : ch_m1)[(b*Nn + sl-1)*3 + c];
    else                      v = (half ? chd_t : chd_m1)[(b*Nn + sl-1-Nn)*3 + c];
    g_coords[idx] = v;
}

// ---------------- tf32 mma GEMM with cp.async 3-stage pipeline ----------------
#define PAD_STR 36
#define SA_FLOATS (128 * PAD_STR)
#define SB_FLOATS (64 * PAD_STR)
#define STAGE_FLOATS (SA_FLOATS + SB_FLOATS)
#define STAGE_BYTES (STAGE_FLOATS * 4)
#define GSM_TOTAL (3 * STAGE_BYTES)           // 82944

__device__ __forceinline__ void cp_chunk(const float* __restrict__ A, const float* __restrict__ W,
                                         int M, int K, int m0, int n0, int k0, uint32_t sStage) {
    int tid = threadIdx.x;
    uint32_t sA = sStage;
    uint32_t sB = sStage + SA_FLOATS * 4;
    #pragma unroll
    for (int i = 0; i < 4; i++) {
        int e = tid + i * 256;
        int r = e >> 3, c4 = e & 7;
        int gm = m0 + r; if (gm > M - 1) gm = M - 1;
        CPA16(sA + (uint32_t)(r * PAD_STR + c4 * 4) * 4, A + (size_t)gm * K + k0 + c4 * 4);
    }
    #pragma unroll
    for (int i = 0; i < 2; i++) {
        int e = tid + i * 256;
        int r = e >> 3, c4 = e & 7;
        CPA16(sB + (uint32_t)(r * PAD_STR + c4 * 4) * 4, W + (size_t)(n0 + r) * K + k0 + c4 * 4);
    }
}

__device__ __forceinline__ void gemm_main(const float* __restrict__ A, const float* __restrict__ W,
                                          int M, int K, int m0, int n0,
                                          uint32_t* smu, uint32_t sbase, float acc[2][4][4]) {
    int NC = K / 32;
    int lane = threadIdx.x & 31, wid = threadIdx.x >> 5;
    int wm = wid & 3, wn = wid >> 2;
    int g = lane >> 2, t = lane & 3;

    cp_chunk(A, W, M, K, m0, n0, 0, sbase);              CPCOMMIT();
    cp_chunk(A, W, M, K, m0, n0, 32, sbase + STAGE_BYTES); CPCOMMIT();

    for (int c = 0; c < NC; c++) {
        if (c + 1 < NC) { CPWAIT1(); } else { CPWAIT0(); }
        __syncthreads();
        if (c + 2 < NC) {
            int st = (c + 2) % 3;
            cp_chunk(A, W, M, K, m0, n0, (c + 2) * 32, sbase + st * STAGE_BYTES);
            CPCOMMIT();
        }
        const uint32_t* cA = smu + (c % 3) * STAGE_FLOATS;
        const uint32_t* cB = cA + SA_FLOATS;

        #pragma unroll
        for (int kk = 0; kk < 4; kk++) {
            uint32_t af[2][4], bf[4][2];
            #pragma unroll
            for (int mi = 0; mi < 2; mi++) {
                int base = (wm * 32 + mi * 16 + g) * PAD_STR + kk * 8 + t;
                af[mi][0] = cA[base];
                af[mi][1] = cA[base + 8 * PAD_STR];
                af[mi][2] = cA[base + 4];
                af[mi][3] = cA[base + 8 * PAD_STR + 4];
            }
            #pragma unroll
            for (int ni = 0; ni < 4; ni++) {
                int bb = (wn * 32 + ni * 8 + g) * PAD_STR + kk * 8 + t;
                bf[ni][0] = cB[bb];
                bf[ni][1] = cB[bb + 4];
            }
            #pragma unroll
            for (int mi = 0; mi < 2; mi++)
                #pragma unroll
                for (int ni = 0; ni < 4; ni++)
                    MMA_TF32(acc[mi][ni], af[mi], bf[ni]);
        }
    }
}

// generic GEMM kernel: mode 0 = plain + bias, mode 2 = exact GELU (output tf32-rounded)
__global__ void __launch_bounds__(256, 2)
gemm_cp(const float* __restrict__ A, const float* __restrict__ W,
        const float* __restrict__ bias, float* __restrict__ C,
        int M, int N, int K, int mode) {
    extern __shared__ uint32_t smu[];
    uint32_t sbase = smem_u32(smu);
    int lane = threadIdx.x & 31, wid = threadIdx.x >> 5;
    int wm = wid & 3, wn = wid >> 2;
    int g = lane >> 2, t = lane & 3;
    int m0 = blockIdx.y * 128, n0 = blockIdx.x * 64;

    float acc[2][4][4] = {};
    gemm_main(A, W, M, K, m0, n0, smu, sbase, acc);

    #pragma unroll
    for (int mi = 0; mi < 2; mi++) {
        #pragma unroll
        for (int half = 0; half < 2; half++) {
            int row = m0 + wm * 32 + mi * 16 + g + half * 8;
            if (row >= M) continue;
            #pragma unroll
            for (int ni = 0; ni < 4; ni++) {
                int col = n0 + wn * 32 + ni * 8 + 2 * t;
                float v0 = acc[mi][ni][half * 2 + 0] + bias[col];
                float v1 = acc[mi][ni][half * 2 + 1] + bias[col + 1];
                if (mode == 2) {
                    v0 = 0.5f * v0 * (1.f + erff(v0 * 0.70710678118654752f));
                    v1 = 0.5f * v1 * (1.f + erff(v1 * 0.70710678118654752f));
                    v0 = rnd_tf32(v0); v1 = rnd_tf32(v1);
                }
                *(float2*)&C[(size_t)row * N + col] = make_float2(v0, v1);
            }
        }
    }
}

// fused QKV + rotary kernel: grid.x = 18 (3 outputs x 6 col-tiles)
// writes head layout [B,H,S,Dh]; q/k rotated in registers (pairs are (ni even, ni odd))
__global__ void __launch_bounds__(256, 2)
qkv_gemm_cp(const float* __restrict__ A,
            const float* __restrict__ wq, const float* __restrict__ wk, const float* __restrict__ wv,
            const float* __restrict__ bq, const float* __restrict__ bk, const float* __restrict__ bv,
            float* __restrict__ q, float* __restrict__ k, float* __restrict__ v) {
    extern __shared__ uint32_t smu[];
    uint32_t sbase = smem_u32(smu);
    int sel = blockIdx.x / 6;
    int n0 = (blockIdx.x % 6) * 64;
    const float* W    = (sel == 0) ? wq : (sel == 1) ? wk : wv;
    const float* bias = (sel == 0) ? bq : (sel == 1) ? bk : bv;
    float* C          = (sel == 0) ? q  : (sel == 1) ? k  : v;

    int lane = threadIdx.x & 31, wid = threadIdx.x >> 5;
    int wm = wid & 3, wn = wid >> 2;
    int g = lane >> 2, t = lane & 3;
    int m0 = blockIdx.y * 128;

    float acc[2][4][4] = {};
    gemm_main(A, W, Mrows, Dd, m0, n0, smu, sbase, acc);

    int wb = n0 + wn * 32;           // warp column base (multiple of 32)

    #pragma unroll
    for (int mi = 0; mi < 2; mi++) {
        #pragma unroll
        for (int half = 0; half < 2; half++) {
            int row = m0 + wm * 32 + mi * 16 + g + half * 8;
            if (row >= Mrows) continue;
            int b = row / Sq, s = row % Sq;

            float vv[4][2];
            #pragma unroll
            for (int ni = 0; ni < 4; ni++) {
                int col = wb + ni * 8 + 2 * t;
                vv[ni][0] = acc[mi][ni][half * 2 + 0] + bias[col];
                vv[ni][1] = acc[mi][ni][half * 2 + 1] + bias[col + 1];
            }

            if (sel < 2) {   // rotate q / k
                const float* co = &g_coords[((size_t)b * Sq + s) * 3];
                #pragma unroll
                for (int p = 0; p < 2; p++) {           // ni pairs (0,1) and (2,3)
                    #pragma unroll
                    for (int u = 0; u < 2; u++) {
                        int colE = wb + p * 16 + 2 * t + u;   // even-ni column
                        int d = colE % DhD;                    // d mod 16 in [0,8)
                        float ang = co[d >> 4] * c_invfreq[d & 7];
                        float sn, cs;
                        __sincosf(ang, &sn, &cs);
                        float x1 = vv[2 * p][u], x2 = vv[2 * p + 1][u];
                        vv[2 * p][u]     = x1 * cs - x2 * sn;
                        vv[2 * p + 1][u] = x1 * sn + x2 * cs;
                    }
                }
            }

            #pragma unroll
            for (int ni = 0; ni < 4; ni++) {
                int col = wb + ni * 8 + 2 * t;
                int h = col / DhD, d = col % DhD;      // col even -> col+1 same head
                *(float2*)&C[(((size_t)b * Hh + h) * Sq + s) * DhD + d] =
                    make_float2(vv[ni][0], vv[ni][1]);
            }
        }
    }
}

// ---------------- tensor-core flash attention ----------------
#define QT 128
#define KT 64
#define SK_STR 52
#define SP_STR 68
#define ATT_SM_U32 (3328 + 3264 + 8704)
#define ATT_SM_BYTES (ATT_SM_U32 * 4)

__global__ void __launch_bounds__(256, 2)
attn_mma_kernel() {
    extern __shared__ uint32_t sm[];
    uint32_t* sK  = sm;
    uint32_t* sVt = sm + 3328;
    uint32_t* sP  = sm + 3328 + 3264;
    uint32_t* sQ  = sP;

    int bh = blockIdx.y;
    int b = bh >> 3, h = bh & 7;
    int q0 = blockIdx.x * QT;
    int tid = threadIdx.x, lane = tid & 31, w = tid >> 5;
    int g = lane >> 2, t = lane & 3;
    int wl = w * 16;

    const float scale = 0.14433756729740645f;
    const float* Qb = &g_q[(size_t)bh * Sq * DhD];
    const float* Kb = &g_k[(size_t)bh * Sq * DhD];
    const float* Vb = &g_v[(size_t)bh * Sq * DhD];

    #pragma unroll
    for (int i = 0; i < 6; i++) {
        int e = tid + i * 256;
        int r = e / 12, c4 = e % 12;
        int gr = q0 + r; if (gr >= Sq) gr = Sq - 1;
        float4 v = *(const float4*)&Qb[(size_t)gr * DhD + c4 * 4];
        uint32_t* dst = &sQ[r * SK_STR + c4 * 4];
        dst[0] = f2tf32(v.x * scale); dst[1] = f2tf32(v.y * scale);
        dst[2] = f2tf32(v.z * scale); dst[3] = f2tf32(v.w * scale);
    }
    __syncthreads();

    uint32_t aQ[6][4];
    #pragma unroll
    for (int kk = 0; kk < 6; kk++) {
        int base = (wl + g) * SK_STR + kk * 8 + t;
        aQ[kk][0] = sQ[base];
        aQ[kk][1] = sQ[base + 8 * SK_STR];
        aQ[kk][2] = sQ[base + 4];
        aQ[kk][3] = sQ[base + 8 * SK_STR + 4];
    }
    __syncthreads();

    int row0 = q0 + wl + g, row1 = row0 + 8;
    int klr0 = (row0 < NM1) ? NM1 : Sq;
    int klr1 = (row1 < NM1) ? NM1 : Sq;

    float m0 = -1e30f, m1 = -1e30f, l0 = 0.f, l1 = 0.f;
    float acc_o[6][4] = {};

    int klmax = (q0 + QT - 1 >= NM1) ? Sq : NM1;
    int nkt = (klmax + KT - 1) / KT;

    for (int kt = 0; kt < nkt; kt++) {
        int kt0 = kt * KT;
        __syncthreads();
        #pragma unroll
        for (int i = 0; i < 3; i++) {
            int e = tid + i * 256;
            int r = e / 12, c4 = e % 12;
            int gk = kt0 + r; if (gk >= Sq) gk = Sq - 1;
            float4 v = *(const float4*)&Kb[(size_t)gk * DhD + c4 * 4];
            uint32_t* dst = &sK[r * SK_STR + c4 * 4];
            dst[0]=f2tf32(v.x); dst[1]=f2tf32(v.y); dst[2]=f2tf32(v.z); dst[3]=f2tf32(v.w);
        }
        #pragma unroll
        for (int i = 0; i < 3; i++) {
            int e = tid + i * 256;
            int r = e / 12, c4 = e % 12;
            int gk = kt0 + r; if (gk >= Sq) gk = Sq - 1;
            float4 v = *(const float4*)&Vb[(size_t)gk * DhD + c4 * 4];
            sVt[(c4*4+0) * SP_STR + r] = f2tf32(v.x);
            sVt[(c4*4+1) * SP_STR + r] = f2tf32(v.y);
            sVt[(c4*4+2) * SP_STR + r] = f2tf32(v.z);
            sVt[(c4*4+3) * SP_STR + r] = f2tf32(v.w);
        }
        __syncthreads();

        float s[8][4];
        #pragma unroll
        for (int ni = 0; ni < 8; ni++) { s[ni][0]=0.f; s[ni][1]=0.f; s[ni][2]=0.f; s[ni][3]=0.f; }
        #pragma unroll
        for (int kk = 0; kk < 6; kk++) {
            #pragma unroll
            for (int ni = 0; ni < 8; ni++) {
                uint32_t bf[2];
                int bb = (ni * 8 + g) * SK_STR + kk * 8 + t;
                bf[0] = sK[bb]; bf[1] = sK[bb + 4];
                MMA_TF32(s[ni], aQ[kk], bf);
            }
        }

        float tm0 = -1e30f, tm1 = -1e30f;
        #pragma unroll
        for (int ni = 0; ni < 8; ni++) {
            int c = kt0 + ni * 8 + 2 * t;
            if (c     >= klr0) s[ni][0] = -1e30f;
            if (c + 1 >= klr0) s[ni][1] = -1e30f;
            if (c     >= klr1) s[ni][2] = -1e30f;
            if (c + 1 >= klr1) s[ni][3] = -1e30f;
            tm0 = fmaxf(tm0, fmaxf(s[ni][0], s[ni][1]));
            tm1 = fmaxf(tm1, fmaxf(s[ni][2], s[ni][3]));
        }
        tm0 = fmaxf(tm0, __shfl_xor_sync(0xffffffffu, tm0, 1));
        tm0 = fmaxf(tm0, __shfl_xor_sync(0xffffffffu, tm0, 2));
        tm1 = fmaxf(tm1, __shfl_xor_sync(0xffffffffu, tm1, 1));
        tm1 = fmaxf(tm1, __shfl_xor_sync(0xffffffffu, tm1, 2));
        float m0n = fmaxf(m0, tm0), m1n = fmaxf(m1, tm1);
        float sf0 = __expf(m0 - m0n), sf1 = __expf(m1 - m1n);
        m0 = m0n; m1 = m1n;

        float sp0 = 0.f, sp1 = 0.f;
        #pragma unroll
        for (int ni = 0; ni < 8; ni++) {
            uint32_t u0 = f2tf32(__expf(s[ni][0] - m0));
            uint32_t u1 = f2tf32(__expf(s[ni][1] - m0));
            uint32_t u2 = f2tf32(__expf(s[ni][2] - m1));
            uint32_t u3 = f2tf32(__expf(s[ni][3] - m1));
            sp0 += __uint_as_float(u0) + __uint_as_float(u1);
            sp1 += __uint_as_float(u2) + __uint_as_float(u3);
            int cl = ni * 8 + 2 * t;
            *(uint2*)&sP[(wl + g)     * SP_STR + cl] = make_uint2(u0, u1);
            *(uint2*)&sP[(wl + g + 8) * SP_STR + cl] = make_uint2(u2, u3);
        }
        sp0 += __shfl_xor_sync(0xffffffffu, sp0, 1);
        sp0 += __shfl_xor_sync(0xffffffffu, sp0, 2);
        sp1 += __shfl_xor_sync(0xffffffffu, sp1, 1);
        sp1 += __shfl_xor_sync(0xffffffffu, sp1, 2);
        l0 = l0 * sf0 + sp0;
        l1 = l1 * sf1 + sp1;
        #pragma unroll
        for (int ni = 0; ni < 6; ni++) {
            acc_o[ni][0] *= sf0; acc_o[ni][1] *= sf0;
            acc_o[ni][2] *= sf1; acc_o[ni][3] *= sf1;
        }
        __syncwarp();

        #pragma unroll
        for (int kk = 0; kk < 8; kk++) {
            uint32_t af[4];
            int base = (wl + g) * SP_STR + kk * 8 + t;
            af[0] = sP[base];
            af[1] = sP[base + 8 * SP_STR];
            af[2] = sP[base + 4];
            af[3] = sP[base + 8 * SP_STR + 4];
            #pragma unroll
            for (int ni = 0; ni < 6; ni++) {
                uint32_t bf[2];
                int bb = (ni * 8 + g) * SP_STR + kk * 8 + t;
                bf[0] = sVt[bb]; bf[1] = sVt[bb + 4];
                MMA_TF32(acc_o[ni], af, bf);
            }
        }
    }

    float inv0 = 1.f / l0, inv1 = 1.f / l1;
    #pragma unroll
    for (int ni = 0; ni < 6; ni++) {
        int col = h * DhD + ni * 8 + 2 * t;
        if (row0 < Sq)
            *(float2*)&g_attn[((size_t)b * Sq + row0) * Dd + col] =
                make_float2(rnd_tf32(acc_o[ni][0] * inv0), rnd_tf32(acc_o[ni][1] * inv0));
        if (row1 < Sq)
            *(float2*)&g_attn[((size_t)b * Sq + row1) * Dd + col] =
                make_float2(rnd_tf32(acc_o[ni][2] * inv1), rnd_tf32(acc_o[ni][3] * inv1));
    }
}

// ---------------- residual + LayerNorm (block per row), tf32-rounded output ----------------
__global__ void __launch_bounds__(128)
add_ln_kernel(const float* X, const float* Yres, float* Out,
              const float* __restrict__ g, const float* __restrict__ be) {
    int row = blockIdx.x;
    __shared__ float red[128];
    const float* x = X + (size_t)row * Dd;
    const float* y = Yres + (size_t)row * Dd;
    float lx[3];
    float sum = 0.f;
    #pragma unroll
    for (int i = 0; i < 3; i++) {
        int d = threadIdx.x + i*128;
        lx[i] = x[d] + y[d];
        sum += lx[i];
    }
    red[threadIdx.x] = sum; __syncthreads();
    for (int st = 64; st > 0; st >>= 1) {
        if (threadIdx.x < st) red[threadIdx.x] += red[threadIdx.x + st];
        __syncthreads();
    }
    float mean = red[0] * (1.f / Dd);
    __syncthreads();
    float vs = 0.f;
    #pragma unroll
    for (int i = 0; i < 3; i++) { float dd = lx[i] - mean; vs += dd*dd; }
    red[threadIdx.x] = vs; __syncthreads();
    for (int st = 64; st > 0; st >>= 1) {
        if (threadIdx.x < st) red[threadIdx.x] += red[threadIdx.x + st];
        __syncthreads();
    }
    float rstd = rsqrtf(red[0] * (1.f / Dd) + 1e-5f);
    #pragma unroll
    for (int i = 0; i < 3; i++) {
        int d = threadIdx.x + i*128;
        Out[(size_t)row*Dd + d] = rnd_tf32((lx[i] - mean) * rstd * g[d] + be[d]);
    }
}

// ---------------- final extraction ----------------
__global__ void extract_kernel(float* __restrict__ out) {
    int idx = blockIdx.x * blockDim.x + threadIdx.x;
    if (idx >= Bz*Tt*Dd) return;
    int d  = idx % Dd;
    int bt = idx / Dd;
    int t  = bt % Tt;
    int b  = bt / Tt;
    out[idx] = g_src[((size_t)b*Sq + (Sq - Tt + t))*Dd + d];
}

// ---------------- host launcher ----------------
extern "C" void kernel_launch(void* const* d_in, const int* in_sizes, int n_in,
                              void* d_out, int out_size) {
    const float* hand_t   = (const float*)d_in[0];
    const float* head_t   = (const float*)d_in[1];
    const float* hand_m1  = (const float*)d_in[2];
    const float* head_m1  = (const float*)d_in[3];
    const float* c_hand_t = (const float*)d_in[4];
    const float* c_head_t = (const float*)d_in[5];
    const float* c_hand_m1= (const float*)d_in[6];
    const float* c_head_m1= (const float*)d_in[7];
    const float* state_t  = (const float*)d_in[8];
    const float* state_m1 = (const float*)d_in[9];
    const float* tr_t     = (const float*)d_in[10];
    const float* tr_m1    = (const float*)d_in[11];
    const float* tokens_m1= (const float*)d_in[12];
    const float* tokens_t = (const float*)d_in[13];
    const float* Wq = (const float*)d_in[14];
    const float* bq = (const float*)d_in[15];
    const float* Wk = (const float*)d_in[16];
    const float* bk = (const float*)d_in[17];
    const float* Wv = (const float*)d_in[18];
    const float* bv = (const float*)d_in[19];
    const float* Wo = (const float*)d_in[20];
    const float* bo = (const float*)d_in[21];
    const float* W1 = (const float*)d_in[22];
    const float* b1 = (const float*)d_in[23];
    const float* W2 = (const float*)d_in[24];
    const float* b2 = (const float*)d_in[25];
    const float* g1 = (const float*)d_in[26];
    const float* be1= (const float*)d_in[27];
    const float* g2 = (const float*)d_in[28];
    const float* be2= (const float*)d_in[29];

    float *src, *q, *k, *v, *attn, *tmp, *ff, *wbuf;
    cudaGetSymbolAddress((void**)&src,  g_src);
    cudaGetSymbolAddress((void**)&q,    g_q);
    cudaGetSymbolAddress((void**)&k,    g_k);
    cudaGetSymbolAddress((void**)&v,    g_v);
    cudaGetSymbolAddress((void**)&attn, g_attn);
    cudaGetSymbolAddress((void**)&tmp,  g_tmp);
    cudaGetSymbolAddress((void**)&ff,   g_ff);
    cudaGetSymbolAddress((void**)&wbuf, g_wbuf);

    float* rwq = wbuf;
    float* rwk = wbuf + (size_t)WSZ_P;
    float* rwv = wbuf + (size_t)2*WSZ_P;
    float* rwo = wbuf + (size_t)3*WSZ_P;
    float* rw1 = wbuf + (size_t)4*WSZ_P;
    float* rw2 = wbuf + (size_t)4*WSZ_P + WSZ_F;

    cudaFuncSetAttribute(gemm_cp,     cudaFuncAttributeMaxDynamicSharedMemorySize, GSM_TOTAL);
    cudaFuncSetAttribute(qkv_gemm_cp, cudaFuncAttributeMaxDynamicSharedMemorySize, GSM_TOTAL);
    cudaFuncSetAttribute(attn_mma_kernel, cudaFuncAttributeMaxDynamicSharedMemorySize, ATT_SM_BYTES);

    // pre-round weights (rna) so cp.async truncation is lossless
    {
        int n4p = WSZ_P / 4, n4f = WSZ_F / 4;
        round_w_kernel<<<(n4p + 255)/256, 256>>>((const float4*)Wq, (float4*)rwq, n4p);
        round_w_kernel<<<(n4p + 255)/256, 256>>>((const float4*)Wk, (float4*)rwk, n4p);
        round_w_kernel<<<(n4p + 255)/256, 256>>>((const float4*)Wv, (float4*)rwv, n4p);
        round_w_kernel<<<(n4p + 255)/256, 256>>>((const float4*)Wo, (float4*)rwo, n4p);
        round_w_kernel<<<(n4f + 255)/256, 256>>>((const float4*)W1, (float4*)rw1, n4f);
        round_w_kernel<<<(n4f + 255)/256, 256>>>((const float4*)W2, (float4*)rw2, n4f);
    }

    build_src_kernel<<<(Mrows*Dd + 255)/256, 256>>>(hand_t, head_t, hand_m1, head_m1,
                                                    state_t, state_m1, tokens_m1, tokens_t);
    build_coords_kernel<<<(Mrows*3 + 255)/256, 256>>>(c_hand_t, c_head_t, c_hand_m1, c_head_m1,
                                                      tr_t, tr_m1);

    dim3 gQKV(18, (Mrows + 127)/128);    // (18, 65)
    dim3 gD(Dd/64,  (Mrows + 127)/128);  // (6, 65)
    dim3 gF(FFd/64, (Mrows + 127)/128);  // (24, 65)
    dim3 gAttn((Sq + QT - 1)/QT, Bz*Hh); // (9, 64)

    for (int l = 0; l < Ll; l++) {
        const float* wq = rwq + (size_t)l*Dd*Dd;  const float* bql = bq + (size_t)l*Dd;
        const float* wk = rwk + (size_t)l*Dd*Dd;  const float* bkl = bk + (size_t)l*Dd;
        const float* wv = rwv + (size_t)l*Dd*Dd;  const float* bvl = bv + (size_t)l*Dd;
        const float* wo = rwo + (size_t)l*Dd*Dd;  const float* bol = bo + (size_t)l*Dd;
        const float* w1 = rw1 + (size_t)l*FFd*Dd; const float* b1l = b1 + (size_t)l*FFd;
        const float* w2 = rw2 + (size_t)l*Dd*FFd; const float* b2l = b2 + (size_t)l*Dd;
        const float* g1l = g1 + (size_t)l*Dd;    const float* be1l = be1 + (size_t)l*Dd;
        const float* g2l = g2 + (size_t)l*Dd;    const float* be2l = be2 + (size_t)l*Dd;

        qkv_gemm_cp<<<gQKV, 256, GSM_TOTAL>>>(src, wq, wk, wv, bql, bkl, bvl, q, k, v);

        attn_mma_kernel<<<gAttn, 256, ATT_SM_BYTES>>>();

        gemm_cp<<<gD, 256, GSM_TOTAL>>>(attn, wo, bol, tmp, Mrows, Dd, Dd, 0);
        add_ln_kernel<<<Mrows, 128>>>(src, tmp, src, g1l, be1l);

        gemm_cp<<<gF, 256, GSM_TOTAL>>>(src, w1, b1l, ff, Mrows, FFd, Dd, 2);
        gemm_cp<<<gD, 256, GSM_TOTAL>>>(ff, w2, b2l, tmp, Mrows, Dd, FFd, 0);
        add_ln_kernel<<<Mrows, 128>>>(src, tmp, src, g2l, be2l);
    }

    extract_kernel<<<(Bz*Tt*Dd + 255)/256, 256>>>((float*)d_out);
}

// round 7
// speedup vs baseline: 3.2011x; 1.0135x over previous
#include <cuda_runtime.h>
#include <cstdint>
#include <math.h>

// ---------------- problem constants ----------------
#define Bz   8
#define Nn   256
#define Dd   384
#define Ll   6
#define Hh   8
#define FFd  1536
#define Tt   4
#define DhD  48
#define NM1  517            // T + 1 + 2N
#define Sq   1034           // 2*NM1
#define Mrows (Bz*Sq)       // 8272

// ---------------- device scratch ----------------
__device__ float g_src   [Mrows*Dd];   // fp32 residual stream
__device__ float g_srcr  [Mrows*Dd];   // tf32(rna)-rounded copy for GEMM input
__device__ float g_coords[Mrows*3];
__device__ float g_q     [Mrows*Dd];
__device__ float g_k     [Mrows*Dd];
__device__ float g_v     [Mrows*Dd];
__device__ float g_attn  [Mrows*Dd];
__device__ float g_tmp   [Mrows*Dd];
__device__ float g_ff    [Mrows*FFd];
// rounded weights: wq|wk|wv|wo (4 * L*D*D) then w1 (L*FF*D) then w2 (L*D*FF)
#define WSZ_P  (Ll*Dd*Dd)        // 884736
#define WSZ_F  (Ll*FFd*Dd)       // 3538944
__device__ float g_wbuf [4*WSZ_P + 2*WSZ_F];

// ---------------- mma / cp.async helpers ----------------
__device__ __forceinline__ uint32_t f2tf32(float f) {
    uint32_t u;
    asm("cvt.rna.tf32.f32 %0, %1;" : "=r"(u) : "f"(f));
    return u;
}
__device__ __forceinline__ float rnd_tf32(float f) { return __uint_as_float(f2tf32(f)); }
__device__ __forceinline__ uint32_t smem_u32(const void* p) {
    uint32_t a;
    asm("{ .reg .u64 t; cvta.to.shared.u64 t, %1; cvt.u32.u64 %0, t; }" : "=r"(a) : "l"(p));
    return a;
}

#define MMA_TF32(d, a, b) \
    asm("mma.sync.aligned.m16n8k8.row.col.f32.tf32.tf32.f32 " \
        "{%0,%1,%2,%3}, {%4,%5,%6,%7}, {%8,%9}, {%0,%1,%2,%3};" \
        : "+f"((d)[0]), "+f"((d)[1]), "+f"((d)[2]), "+f"((d)[3]) \
        : "r"((a)[0]), "r"((a)[1]), "r"((a)[2]), "r"((a)[3]), \
          "r"((b)[0]), "r"((b)[1]))

#define CPA16(dst, src) \
    asm volatile("cp.async.cg.shared.global [%0], [%1], 16;" :: "r"(dst), "l"(src) : "memory")
#define CPCOMMIT() asm volatile("cp.async.commit_group;" ::: "memory")
#define CPWAIT0()  asm volatile("cp.async.wait_group 0;" ::: "memory")
#define CPWAIT1()  asm volatile("cp.async.wait_group 1;" ::: "memory")

__constant__ float c_invfreq[8] = {
    1.0f, 0.31622776601683794f, 0.1f, 0.031622776601683794f,
    0.01f, 0.0031622776601683794f, 0.001f, 0.00031622776601683794f
};

// ---------------- weight pre-rounding (once per launch) ----------------
__global__ void round_w_kernel(const float4* __restrict__ in, float4* __restrict__ out, int n4) {
    int i = blockIdx.x * blockDim.x + threadIdx.x;
    if (i >= n4) return;
    float4 v = in[i];
    v.x = rnd_tf32(v.x); v.y = rnd_tf32(v.y);
    v.z = rnd_tf32(v.z); v.w = rnd_tf32(v.w);
    out[i] = v;
}

// ---------------- build src / coords ----------------
__global__ void build_src_kernel(const float* __restrict__ hand_t, const float* __restrict__ head_t,
                                 const float* __restrict__ hand_m1, const float* __restrict__ head_m1,
                                 const float* __restrict__ state_t, const float* __restrict__ state_m1,
                                 const float* __restrict__ tok_m1, const float* __restrict__ tok_t) {
    int idx = blockIdx.x * blockDim.x + threadIdx.x;
    if (idx >= Mrows * Dd) return;
    int d  = idx % Dd;
    int bs = idx / Dd;
    int s  = bs % Sq;
    int b  = bs / Sq;
    int half = (s >= NM1) ? 1 : 0;
    int sl = s - half * NM1;
    float v;
    if (sl == 0)            v = (half ? state_t : state_m1)[b*Dd + d];
    else if (sl <= Nn)      v = (half ? hand_t : hand_m1)[(b*Nn + sl-1)*Dd + d];
    else if (sl <= 2*Nn)    v = (half ? head_t : head_m1)[(b*Nn + sl-1-Nn)*Dd + d];
    else                    v = (half ? tok_t : tok_m1)[(sl-1-2*Nn)*Dd + d];
    g_src[idx]  = v;
    g_srcr[idx] = rnd_tf32(v);
}

__global__ void build_coords_kernel(const float* __restrict__ ch_t, const float* __restrict__ chd_t,
                                    const float* __restrict__ ch_m1, const float* __restrict__ chd_m1,
                                    const float* __restrict__ tr_t, const float* __restrict__ tr_m1) {
    int idx = blockIdx.x * blockDim.x + threadIdx.x;
    if (idx >= Mrows * 3) return;
    int c  = idx % 3;
    int bs = idx / 3;
    int s  = bs % Sq;
    int b  = bs / Sq;
    int half = (s >= NM1) ? 1 : 0;
    int sl = s - half * NM1;
    float v;
    if (sl == 0 || sl > 2*Nn) v = (half ? tr_t : tr_m1)[b*3 + c];
    else if (sl <= Nn)        v = (half ? ch_t : ch_m1)[(b*Nn + sl-1)*3 + c];
    else                      v = (half ? chd_t : chd_m1)[(b*Nn + sl-1-Nn)*3 + c];
    g_coords[idx] = v;
}

// ---------------- tf32 mma GEMM with cp.async 3-stage pipeline ----------------
#define PAD_STR 36
#define SA_FLOATS (128 * PAD_STR)
#define SB_FLOATS (64 * PAD_STR)
#define STAGE_FLOATS (SA_FLOATS + SB_FLOATS)
#define STAGE_BYTES (STAGE_FLOATS * 4)
#define GSM_TOTAL (3 * STAGE_BYTES)           // 82944

__device__ __forceinline__ void cp_chunk(const float* __restrict__ A, const float* __restrict__ W,
                                         int M, int K, int m0, int n0, int k0, uint32_t sStage) {
    int tid = threadIdx.x;
    uint32_t sA = sStage;
    uint32_t sB = sStage + SA_FLOATS * 4;
    #pragma unroll
    for (int i = 0; i < 4; i++) {
        int e = tid + i * 256;
        int r = e >> 3, c4 = e & 7;
        int gm = m0 + r; if (gm > M - 1) gm = M - 1;
        CPA16(sA + (uint32_t)(r * PAD_STR + c4 * 4) * 4, A + (size_t)gm * K + k0 + c4 * 4);
    }
    #pragma unroll
    for (int i = 0; i < 2; i++) {
        int e = tid + i * 256;
        int r = e >> 3, c4 = e & 7;
        CPA16(sB + (uint32_t)(r * PAD_STR + c4 * 4) * 4, W + (size_t)(n0 + r) * K + k0 + c4 * 4);
    }
}

__device__ __forceinline__ void gemm_main(const float* __restrict__ A, const float* __restrict__ W,
                                          int M, int K, int m0, int n0,
                                          uint32_t* smu, uint32_t sbase, float acc[2][4][4]) {
    int NC = K / 32;
    int lane = threadIdx.x & 31, wid = threadIdx.x >> 5;
    int wm = wid & 3, wn = wid >> 2;
    int g = lane >> 2, t = lane & 3;

    cp_chunk(A, W, M, K, m0, n0, 0, sbase);              CPCOMMIT();
    cp_chunk(A, W, M, K, m0, n0, 32, sbase + STAGE_BYTES); CPCOMMIT();

    for (int c = 0; c < NC; c++) {
        if (c + 1 < NC) { CPWAIT1(); } else { CPWAIT0(); }
        __syncthreads();
        if (c + 2 < NC) {
            int st = (c + 2) % 3;
            cp_chunk(A, W, M, K, m0, n0, (c + 2) * 32, sbase + st * STAGE_BYTES);
            CPCOMMIT();
        }
        const uint32_t* cA = smu + (c % 3) * STAGE_FLOATS;
        const uint32_t* cB = cA + SA_FLOATS;

        #pragma unroll
        for (int kk = 0; kk < 4; kk++) {
            uint32_t af[2][4], bf[4][2];
            #pragma unroll
            for (int mi = 0; mi < 2; mi++) {
                int base = (wm * 32 + mi * 16 + g) * PAD_STR + kk * 8 + t;
                af[mi][0] = cA[base];
                af[mi][1] = cA[base + 8 * PAD_STR];
                af[mi][2] = cA[base + 4];
                af[mi][3] = cA[base + 8 * PAD_STR + 4];
            }
            #pragma unroll
            for (int ni = 0; ni < 4; ni++) {
                int bb = (wn * 32 + ni * 8 + g) * PAD_STR + kk * 8 + t;
                bf[ni][0] = cB[bb];
                bf[ni][1] = cB[bb + 4];
            }
            #pragma unroll
            for (int mi = 0; mi < 2; mi++)
                #pragma unroll
                for (int ni = 0; ni < 4; ni++)
                    MMA_TF32(acc[mi][ni], af[mi], bf[ni]);
        }
    }
}

// generic GEMM kernel: mode 0 = plain + bias, mode 2 = exact GELU (output tf32-rounded)
__global__ void __launch_bounds__(256, 2)
gemm_cp(const float* __restrict__ A, const float* __restrict__ W,
        const float* __restrict__ bias, float* __restrict__ C,
        int M, int N, int K, int mode) {
    extern __shared__ uint32_t smu[];
    uint32_t sbase = smem_u32(smu);
    int lane = threadIdx.x & 31, wid = threadIdx.x >> 5;
    int wm = wid & 3, wn = wid >> 2;
    int g = lane >> 2, t = lane & 3;
    int m0 = blockIdx.y * 128, n0 = blockIdx.x * 64;

    float acc[2][4][4] = {};
    gemm_main(A, W, M, K, m0, n0, smu, sbase, acc);

    #pragma unroll
    for (int mi = 0; mi < 2; mi++) {
        #pragma unroll
        for (int half = 0; half < 2; half++) {
            int row = m0 + wm * 32 + mi * 16 + g + half * 8;
            if (row >= M) continue;
            #pragma unroll
            for (int ni = 0; ni < 4; ni++) {
                int col = n0 + wn * 32 + ni * 8 + 2 * t;
                float v0 = acc[mi][ni][half * 2 + 0] + bias[col];
                float v1 = acc[mi][ni][half * 2 + 1] + bias[col + 1];
                if (mode == 2) {
                    v0 = 0.5f * v0 * (1.f + erff(v0 * 0.70710678118654752f));
                    v1 = 0.5f * v1 * (1.f + erff(v1 * 0.70710678118654752f));
                    v0 = rnd_tf32(v0); v1 = rnd_tf32(v1);
                }
                *(float2*)&C[(size_t)row * N + col] = make_float2(v0, v1);
            }
        }
    }
}

// fused QKV + rotary kernel: grid.x = 18 (3 outputs x 6 col-tiles)
__global__ void __launch_bounds__(256, 2)
qkv_gemm_cp(const float* __restrict__ A,
            const float* __restrict__ wq, const float* __restrict__ wk, const float* __restrict__ wv,
            const float* __restrict__ bq, const float* __restrict__ bk, const float* __restrict__ bv,
            float* __restrict__ q, float* __restrict__ k, float* __restrict__ v) {
    extern __shared__ uint32_t smu[];
    uint32_t sbase = smem_u32(smu);
    int sel = blockIdx.x / 6;
    int n0 = (blockIdx.x % 6) * 64;
    const float* W    = (sel == 0) ? wq : (sel == 1) ? wk : wv;
    const float* bias = (sel == 0) ? bq : (sel == 1) ? bk : bv;
    float* C          = (sel == 0) ? q  : (sel == 1) ? k  : v;

    int lane = threadIdx.x & 31, wid = threadIdx.x >> 5;
    int wm = wid & 3, wn = wid >> 2;
    int g = lane >> 2, t = lane & 3;
    int m0 = blockIdx.y * 128;

    float acc[2][4][4] = {};
    gemm_main(A, W, Mrows, Dd, m0, n0, smu, sbase, acc);

    int wb = n0 + wn * 32;

    #pragma unroll
    for (int mi = 0; mi < 2; mi++) {
        #pragma unroll
        for (int half = 0; half < 2; half++) {
            int row = m0 + wm * 32 + mi * 16 + g + half * 8;
            if (row >= Mrows) continue;
            int b = row / Sq, s = row % Sq;

            float vv[4][2];
            #pragma unroll
            for (int ni = 0; ni < 4; ni++) {
                int col = wb + ni * 8 + 2 * t;
                vv[ni][0] = acc[mi][ni][half * 2 + 0] + bias[col];
                vv[ni][1] = acc[mi][ni][half * 2 + 1] + bias[col + 1];
            }

            if (sel < 2) {   // rotate q / k in registers
                const float* co = &g_coords[((size_t)b * Sq + s) * 3];
                #pragma unroll
                for (int p = 0; p < 2; p++) {
                    #pragma unroll
                    for (int u = 0; u < 2; u++) {
                        int colE = wb + p * 16 + 2 * t + u;
                        int d = colE % DhD;
                        float ang = co[d >> 4] * c_invfreq[d & 7];
                        float sn, cs;
                        __sincosf(ang, &sn, &cs);
                        float x1 = vv[2 * p][u], x2 = vv[2 * p + 1][u];
                        vv[2 * p][u]     = x1 * cs - x2 * sn;
                        vv[2 * p + 1][u] = x1 * sn + x2 * cs;
                    }
                }
            }

            #pragma unroll
            for (int ni = 0; ni < 4; ni++) {
                int col = wb + ni * 8 + 2 * t;
                int h = col / DhD, d = col % DhD;
                *(float2*)&C[(((size_t)b * Hh + h) * Sq + s) * DhD + d] =
                    make_float2(vv[ni][0], vv[ni][1]);
            }
        }
    }
}

// ---------------- tensor-core flash attention ----------------
#define QT 128
#define KT 64
#define SK_STR 52
#define SP_STR 68
#define ATT_SM_U32 (3328 + 3264 + 8704)
#define ATT_SM_BYTES (ATT_SM_U32 * 4)

__global__ void __launch_bounds__(256, 2)
attn_mma_kernel() {
    extern __shared__ uint32_t sm[];
    uint32_t* sK  = sm;
    uint32_t* sVt = sm + 3328;
    uint32_t* sP  = sm + 3328 + 3264;
    uint32_t* sQ  = sP;

    int bh = blockIdx.y;
    int b = bh >> 3, h = bh & 7;
    int q0 = blockIdx.x * QT;
    int tid = threadIdx.x, lane = tid & 31, w = tid >> 5;
    int g = lane >> 2, t = lane & 3;
    int wl = w * 16;

    const float scale = 0.14433756729740645f;
    const float* Qb = &g_q[(size_t)bh * Sq * DhD];
    const float* Kb = &g_k[(size_t)bh * Sq * DhD];
    const float* Vb = &g_v[(size_t)bh * Sq * DhD];

    #pragma unroll
    for (int i = 0; i < 6; i++) {
        int e = tid + i * 256;
        int r = e / 12, c4 = e % 12;
        int gr = q0 + r; if (gr >= Sq) gr = Sq - 1;
        float4 v = *(const float4*)&Qb[(size_t)gr * DhD + c4 * 4];
        uint32_t* dst = &sQ[r * SK_STR + c4 * 4];
        dst[0] = f2tf32(v.x * scale); dst[1] = f2tf32(v.y * scale);
        dst[2] = f2tf32(v.z * scale); dst[3] = f2tf32(v.w * scale);
    }
    __syncthreads();

    uint32_t aQ[6][4];
    #pragma unroll
    for (int kk = 0; kk < 6; kk++) {
        int base = (wl + g) * SK_STR + kk * 8 + t;
        aQ[kk][0] = sQ[base];
        aQ[kk][1] = sQ[base + 8 * SK_STR];
        aQ[kk][2] = sQ[base + 4];
        aQ[kk][3] = sQ[base + 8 * SK_STR + 4];
    }
    __syncthreads();

    int row0 = q0 + wl + g, row1 = row0 + 8;
    int klr0 = (row0 < NM1) ? NM1 : Sq;
    int klr1 = (row1 < NM1) ? NM1 : Sq;

    float m0 = -1e30f, m1 = -1e30f, l0 = 0.f, l1 = 0.f;
    float acc_o[6][4] = {};

    int klmax = (q0 + QT - 1 >= NM1) ? Sq : NM1;
    int nkt = (klmax + KT - 1) / KT;

    for (int kt = 0; kt < nkt; kt++) {
        int kt0 = kt * KT;
        __syncthreads();
        #pragma unroll
        for (int i = 0; i < 3; i++) {
            int e = tid + i * 256;
            int r = e / 12, c4 = e % 12;
            int gk = kt0 + r; if (gk >= Sq) gk = Sq - 1;
            float4 v = *(const float4*)&Kb[(size_t)gk * DhD + c4 * 4];
            uint32_t* dst = &sK[r * SK_STR + c4 * 4];
            dst[0]=f2tf32(v.x); dst[1]=f2tf32(v.y); dst[2]=f2tf32(v.z); dst[3]=f2tf32(v.w);
        }
        #pragma unroll
        for (int i = 0; i < 3; i++) {
            int e = tid + i * 256;
            int r = e / 12, c4 = e % 12;
            int gk = kt0 + r; if (gk >= Sq) gk = Sq - 1;
            float4 v = *(const float4*)&Vb[(size_t)gk * DhD + c4 * 4];
            sVt[(c4*4+0) * SP_STR + r] = f2tf32(v.x);
            sVt[(c4*4+1) * SP_STR + r] = f2tf32(v.y);
            sVt[(c4*4+2) * SP_STR + r] = f2tf32(v.z);
            sVt[(c4*4+3) * SP_STR + r] = f2tf32(v.w);
        }
        __syncthreads();

        float s[8][4];
        #pragma unroll
        for (int ni = 0; ni < 8; ni++) { s[ni][0]=0.f; s[ni][1]=0.f; s[ni][2]=0.f; s[ni][3]=0.f; }
        #pragma unroll
        for (int kk = 0; kk < 6; kk++) {
            #pragma unroll
            for (int ni = 0; ni < 8; ni++) {
                uint32_t bf[2];
                int bb = (ni * 8 + g) * SK_STR + kk * 8 + t;
                bf[0] = sK[bb]; bf[1] = sK[bb + 4];
                MMA_TF32(s[ni], aQ[kk], bf);
            }
        }

        float tm0 = -1e30f, tm1 = -1e30f;
        #pragma unroll
        for (int ni = 0; ni < 8; ni++) {
            int c = kt0 + ni * 8 + 2 * t;
            if (c     >= klr0) s[ni][0] = -1e30f;
            if (c + 1 >= klr0) s[ni][1] = -1e30f;
            if (c     >= klr1) s[ni][2] = -1e30f;
            if (c + 1 >= klr1) s[ni][3] = -1e30f;
            tm0 = fmaxf(tm0, fmaxf(s[ni][0], s[ni][1]));
            tm1 = fmaxf(tm1, fmaxf(s[ni][2], s[ni][3]));
        }
        tm0 = fmaxf(tm0, __shfl_xor_sync(0xffffffffu, tm0, 1));
        tm0 = fmaxf(tm0, __shfl_xor_sync(0xffffffffu, tm0, 2));
        tm1 = fmaxf(tm1, __shfl_xor_sync(0xffffffffu, tm1, 1));
        tm1 = fmaxf(tm1, __shfl_xor_sync(0xffffffffu, tm1, 2));
        float m0n = fmaxf(m0, tm0), m1n = fmaxf(m1, tm1);
        float sf0 = __expf(m0 - m0n), sf1 = __expf(m1 - m1n);
        m0 = m0n; m1 = m1n;

        float sp0 = 0.f, sp1 = 0.f;
        #pragma unroll
        for (int ni = 0; ni < 8; ni++) {
            uint32_t u0 = f2tf32(__expf(s[ni][0] - m0));
            uint32_t u1 = f2tf32(__expf(s[ni][1] - m0));
            uint32_t u2 = f2tf32(__expf(s[ni][2] - m1));
            uint32_t u3 = f2tf32(__expf(s[ni][3] - m1));
            sp0 += __uint_as_float(u0) + __uint_as_float(u1);
            sp1 += __uint_as_float(u2) + __uint_as_float(u3);
            int cl = ni * 8 + 2 * t;
            *(uint2*)&sP[(wl + g)     * SP_STR + cl] = make_uint2(u0, u1);
            *(uint2*)&sP[(wl + g + 8) * SP_STR + cl] = make_uint2(u2, u3);
        }
        sp0 += __shfl_xor_sync(0xffffffffu, sp0, 1);
        sp0 += __shfl_xor_sync(0xffffffffu, sp0, 2);
        sp1 += __shfl_xor_sync(0xffffffffu, sp1, 1);
        sp1 += __shfl_xor_sync(0xffffffffu, sp1, 2);
        l0 = l0 * sf0 + sp0;
        l1 = l1 * sf1 + sp1;
        #pragma unroll
        for (int ni = 0; ni < 6; ni++) {
            acc_o[ni][0] *= sf0; acc_o[ni][1] *= sf0;
            acc_o[ni][2] *= sf1; acc_o[ni][3] *= sf1;
        }
        __syncwarp();

        #pragma unroll
        for (int kk = 0; kk < 8; kk++) {
            uint32_t af[4];
            int base = (wl + g) * SP_STR + kk * 8 + t;
            af[0] = sP[base];
            af[1] = sP[base + 8 * SP_STR];
            af[2] = sP[base + 4];
            af[3] = sP[base + 8 * SP_STR + 4];
            #pragma unroll
            for (int ni = 0; ni < 6; ni++) {
                uint32_t bf[2];
                int bb = (ni * 8 + g) * SP_STR + kk * 8 + t;
                bf[0] = sVt[bb]; bf[1] = sVt[bb + 4];
                MMA_TF32(acc_o[ni], af, bf);
            }
        }
    }

    float inv0 = 1.f / l0, inv1 = 1.f / l1;
    #pragma unroll
    for (int ni = 0; ni < 6; ni++) {
        int col = h * DhD + ni * 8 + 2 * t;
        if (row0 < Sq)
            *(float2*)&g_attn[((size_t)b * Sq + row0) * Dd + col] =
                make_float2(rnd_tf32(acc_o[ni][0] * inv0), rnd_tf32(acc_o[ni][1] * inv0));
        if (row1 < Sq)
            *(float2*)&g_attn[((size_t)b * Sq + row1) * Dd + col] =
                make_float2(rnd_tf32(acc_o[ni][2] * inv1), rnd_tf32(acc_o[ni][3] * inv1));
    }
}

// ---------------- residual + LayerNorm: warp per row, dual output ----------------
// Out  = fp32 (residual stream), OutR = tf32-rounded (GEMM input)
__global__ void __launch_bounds__(256)
add_ln_kernel(const float* __restrict__ X, const float* __restrict__ Yres,
              float* __restrict__ Out, float* __restrict__ OutR,
              const float* __restrict__ g, const float* __restrict__ be) {
    int warp = threadIdx.x >> 5, lane = threadIdx.x & 31;
    int row = blockIdx.x * 8 + warp;                 // Mrows = 1034*8 exactly
    const float4* x = (const float4*)(X + (size_t)row * Dd);
    const float4* y = (const float4*)(Yres + (size_t)row * Dd);

    float4 lx[3];
    float sum = 0.f;
    #pragma unroll
    for (int i = 0; i < 3; i++) {
        float4 a = x[lane + i * 32];
        float4 b = y[lane + i * 32];
        a.x += b.x; a.y += b.y; a.z += b.z; a.w += b.w;
        lx[i] = a;
        sum += a.x + a.y + a.z + a.w;
    }
    #pragma unroll
    for (int s = 16; s > 0; s >>= 1) sum += __shfl_xor_sync(0xffffffffu, sum, s);
    float mean = sum * (1.f / Dd);

    float vs = 0.f;
    #pragma unroll
    for (int i = 0; i < 3; i++) {
        float dx = lx[i].x - mean, dy = lx[i].y - mean,
              dz = lx[i].z - mean, dw = lx[i].w - mean;
        vs += dx*dx + dy*dy + dz*dz + dw*dw;
    }
    #pragma unroll
    for (int s = 16; s > 0; s >>= 1) vs += __shfl_xor_sync(0xffffffffu, vs, s);
    float rstd = rsqrtf(vs * (1.f / Dd) + 1e-5f);

    const float4* gg = (const float4*)g;
    const float4* bb = (const float4*)be;
    float4* o  = (float4*)(Out  + (size_t)row * Dd);
    float4* orr= (float4*)(OutR + (size_t)row * Dd);
    #pragma unroll
    for (int i = 0; i < 3; i++) {
        float4 gv = gg[lane + i * 32];
        float4 bv = bb[lane + i * 32];
        float4 r;
        r.x = (lx[i].x - mean) * rstd * gv.x + bv.x;
        r.y = (lx[i].y - mean) * rstd * gv.y + bv.y;
        r.z = (lx[i].z - mean) * rstd * gv.z + bv.z;
        r.w = (lx[i].w - mean) * rstd * gv.w + bv.w;
        o[lane + i * 32] = r;
        float4 rr;
        rr.x = rnd_tf32(r.x); rr.y = rnd_tf32(r.y);
        rr.z = rnd_tf32(r.z); rr.w = rnd_tf32(r.w);
        orr[lane + i * 32] = rr;
    }
}

// ---------------- final extraction ----------------
__global__ void extract_kernel(float* __restrict__ out) {
    int idx = blockIdx.x * blockDim.x + threadIdx.x;
    if (idx >= Bz*Tt*Dd) return;
    int d  = idx % Dd;
    int bt = idx / Dd;
    int t  = bt % Tt;
    int b  = bt / Tt;
    out[idx] = g_src[((size_t)b*Sq + (Sq - Tt + t))*Dd + d];
}

// ---------------- host launcher ----------------
extern "C" void kernel_launch(void* const* d_in, const int* in_sizes, int n_in,
                              void* d_out, int out_size) {
    const float* hand_t   = (const float*)d_in[0];
    const float* head_t   = (const float*)d_in[1];
    const float* hand_m1  = (const float*)d_in[2];
    const float* head_m1  = (const float*)d_in[3];
    const float* c_hand_t = (const float*)d_in[4];
    const float* c_head_t = (const float*)d_in[5];
    const float* c_hand_m1= (const float*)d_in[6];
    const float* c_head_m1= (const float*)d_in[7];
    const float* state_t  = (const float*)d_in[8];
    const float* state_m1 = (const float*)d_in[9];
    const float* tr_t     = (const float*)d_in[10];
    const float* tr_m1    = (const float*)d_in[11];
    const float* tokens_m1= (const float*)d_in[12];
    const float* tokens_t = (const float*)d_in[13];
    const float* Wq = (const float*)d_in[14];
    const float* bq = (const float*)d_in[15];
    const float* Wk = (const float*)d_in[16];
    const float* bk = (const float*)d_in[17];
    const float* Wv = (const float*)d_in[18];
    const float* bv = (const float*)d_in[19];
    const float* Wo = (const float*)d_in[20];
    const float* bo = (const float*)d_in[21];
    const float* W1 = (const float*)d_in[22];
    const float* b1 = (const float*)d_in[23];
    const float* W2 = (const float*)d_in[24];
    const float* b2 = (const float*)d_in[25];
    const float* g1 = (const float*)d_in[26];
    const float* be1= (const float*)d_in[27];
    const float* g2 = (const float*)d_in[28];
    const float* be2= (const float*)d_in[29];

    float *src, *srcr, *q, *k, *v, *attn, *tmp, *ff, *wbuf;
    cudaGetSymbolAddress((void**)&src,  g_src);
    cudaGetSymbolAddress((void**)&srcr, g_srcr);
    cudaGetSymbolAddress((void**)&q,    g_q);
    cudaGetSymbolAddress((void**)&k,    g_k);
    cudaGetSymbolAddress((void**)&v,    g_v);
    cudaGetSymbolAddress((void**)&attn, g_attn);
    cudaGetSymbolAddress((void**)&tmp,  g_tmp);
    cudaGetSymbolAddress((void**)&ff,   g_ff);
    cudaGetSymbolAddress((void**)&wbuf, g_wbuf);

    float* rwq = wbuf;
    float* rwk = wbuf + (size_t)WSZ_P;
    float* rwv = wbuf + (size_t)2*WSZ_P;
    float* rwo = wbuf + (size_t)3*WSZ_P;
    float* rw1 = wbuf + (size_t)4*WSZ_P;
    float* rw2 = wbuf + (size_t)4*WSZ_P + WSZ_F;

    cudaFuncSetAttribute(gemm_cp,     cudaFuncAttributeMaxDynamicSharedMemorySize, GSM_TOTAL);
    cudaFuncSetAttribute(qkv_gemm_cp, cudaFuncAttributeMaxDynamicSharedMemorySize, GSM_TOTAL);
    cudaFuncSetAttribute(attn_mma_kernel, cudaFuncAttributeMaxDynamicSharedMemorySize, ATT_SM_BYTES);

    {
        int n4p = WSZ_P / 4, n4f = WSZ_F / 4;
        round_w_kernel<<<(n4p + 255)/256, 256>>>((const float4*)Wq, (float4*)rwq, n4p);
        round_w_kernel<<<(n4p + 255)/256, 256>>>((const float4*)Wk, (float4*)rwk, n4p);
        round_w_kernel<<<(n4p + 255)/256, 256>>>((const float4*)Wv, (float4*)rwv, n4p);
        round_w_kernel<<<(n4p + 255)/256, 256>>>((const float4*)Wo, (float4*)rwo, n4p);
        round_w_kernel<<<(n4f + 255)/256, 256>>>((const float4*)W1, (float4*)rw1, n4f);
        round_w_kernel<<<(n4f + 255)/256, 256>>>((const float4*)W2, (float4*)rw2, n4f);
    }

    build_src_kernel<<<(Mrows*Dd + 255)/256, 256>>>(hand_t, head_t, hand_m1, head_m1,
                                                    state_t, state_m1, tokens_m1, tokens_t);
    build_coords_kernel<<<(Mrows*3 + 255)/256, 256>>>(c_hand_t, c_head_t, c_hand_m1, c_head_m1,
                                                      tr_t, tr_m1);

    dim3 gQKV(18, (Mrows + 127)/128);    // (18, 65)
    dim3 gD(Dd/64,  (Mrows + 127)/128);  // (6, 65)
    dim3 gF(FFd/64, (Mrows + 127)/128);  // (24, 65)
    dim3 gAttn((Sq + QT - 1)/QT, Bz*Hh); // (9, 64)

    for (int l = 0; l < Ll; l++) {
        const float* wq = rwq + (size_t)l*Dd*Dd;  const float* bql = bq + (size_t)l*Dd;
        const float* wk = rwk + (size_t)l*Dd*Dd;  const float* bkl = bk + (size_t)l*Dd;
        const float* wv = rwv + (size_t)l*Dd*Dd;  const float* bvl = bv + (size_t)l*Dd;
        const float* wo = rwo + (size_t)l*Dd*Dd;  const float* bol = bo + (size_t)l*Dd;
        const float* w1 = rw1 + (size_t)l*FFd*Dd; const float* b1l = b1 + (size_t)l*FFd;
        const float* w2 = rw2 + (size_t)l*Dd*FFd; const float* b2l = b2 + (size_t)l*Dd;
        const float* g1l = g1 + (size_t)l*Dd;    const float* be1l = be1 + (size_t)l*Dd;
        const float* g2l = g2 + (size_t)l*Dd;    const float* be2l = be2 + (size_t)l*Dd;

        qkv_gemm_cp<<<gQKV, 256, GSM_TOTAL>>>(srcr, wq, wk, wv, bql, bkl, bvl, q, k, v);

        attn_mma_kernel<<<gAttn, 256, ATT_SM_BYTES>>>();

        gemm_cp<<<gD, 256, GSM_TOTAL>>>(attn, wo, bol, tmp, Mrows, Dd, Dd, 0);
        add_ln_kernel<<<Mrows/8, 256>>>(src, tmp, src, srcr, g1l, be1l);

        gemm_cp<<<gF, 256, GSM_TOTAL>>>(srcr, w1, b1l, ff, Mrows, FFd, Dd, 2);
        gemm_cp<<<gD, 256, GSM_TOTAL>>>(ff, w2, b2l, tmp, Mrows, Dd, FFd, 0);
        add_ln_kernel<<<Mrows/8, 256>>>(src, tmp, src, srcr, g2l, be2l);
    }

    extract_kernel<<<(Bz*Tt*Dd + 255)/256, 256>>>((float*)d_out);
}